// round 12
// baseline (speedup 1.0000x reference)
#include <cuda_runtime.h>
#include <math.h>
#include <stdint.h>

#define BATCH 8
#define SEQ 1370
#define DIM 1024
#define HEADS 16
#define HDIM 64
#define MROWS (BATCH * SEQ)   // 10960

// Q pre-scale: 1/sqrt(64) * log2(e)  (softmax computed in base-2 domain)
#define QSCALE 0.18033688011112042f

// Scratch (allocation-free: device globals)
__device__ __align__(256) float g_q[BATCH * HEADS * SEQ * HDIM];   // [B,H,S,Dh] tf32, pre-scaled
__device__ __align__(256) float g_k[BATCH * HEADS * SEQ * HDIM];
__device__ __align__(256) float g_v[BATCH * HEADS * SEQ * HDIM];
__device__ __align__(256) float g_ctx[BATCH * SEQ * DIM];          // [B,S,D] tf32
__device__ __align__(256) float g_xr[MROWS * DIM];                 // x rounded to tf32
__device__ __align__(256) float g_wr[4 * DIM * DIM];               // Wq,Wk,Wv,Wo rounded [k][n]

__device__ __forceinline__ float to_tf32(float x) {
    float r; asm("cvt.rna.tf32.f32 %0, %1;" : "=f"(r) : "f"(x)); return r;
}
__device__ __forceinline__ unsigned fu(float x) { return __float_as_uint(x); }
__device__ __forceinline__ float ex2(float x) {
    float r; asm("ex2.approx.f32 %0, %1;" : "=f"(r) : "f"(x)); return r;
}

__device__ __forceinline__ void mma_tf32(float c[4],
    unsigned a0, unsigned a1, unsigned a2, unsigned a3,
    unsigned b0, unsigned b1)
{
    asm volatile(
        "mma.sync.aligned.m16n8k8.row.col.f32.tf32.tf32.f32 "
        "{%0,%1,%2,%3}, {%4,%5,%6,%7}, {%8,%9}, {%0,%1,%2,%3};"
        : "+f"(c[0]), "+f"(c[1]), "+f"(c[2]), "+f"(c[3])
        : "r"(a0), "r"(a1), "r"(a2), "r"(a3), "r"(b0), "r"(b1));
}

// ---- cp.async helpers ----
__device__ __forceinline__ void cp16(void* smem_dst, const void* gsrc, bool pred) {
    unsigned d = (unsigned)__cvta_generic_to_shared(smem_dst);
    int sz = pred ? 16 : 0;
    asm volatile("cp.async.cg.shared.global [%0], [%1], 16, %2;\n"
                 :: "r"(d), "l"(gsrc), "r"(sz));
}
#define CP_COMMIT() asm volatile("cp.async.commit_group;\n")
#define CP_WAIT0()  asm volatile("cp.async.wait_group 0;\n" ::: "memory")
#define CP_WAIT1()  asm volatile("cp.async.wait_group 1;\n" ::: "memory")

// ---------------------------------------------------------------------------
// Pre-rounding passes
// ---------------------------------------------------------------------------
__global__ __launch_bounds__(256) void round_x(const float* __restrict__ x)
{
    int i = blockIdx.x * blockDim.x + threadIdx.x;
    if (i >= MROWS * DIM / 4) return;
    float4 v = ((const float4*)x)[i];
    ((float4*)g_xr)[i] = make_float4(to_tf32(v.x), to_tf32(v.y), to_tf32(v.z), to_tf32(v.w));
}

__global__ __launch_bounds__(256) void round_w(
    const float* __restrict__ wq, const float* __restrict__ wk,
    const float* __restrict__ wv, const float* __restrict__ wo)
{
    int i = blockIdx.x * blockDim.x + threadIdx.x;
    int w = i >> 18;
    int j = i & 262143;
    const float* s = (w == 0) ? wq : (w == 1) ? wk : (w == 2) ? wv : wo;
    float4 v = ((const float4*)s)[j];
    ((float4*)g_wr)[i] = make_float4(to_tf32(v.x), to_tf32(v.y), to_tf32(v.z), to_tf32(v.w));
}

// ---------------------------------------------------------------------------
// TF32 GEMM, 3-stage cp.async pipeline (R8 proven). C = A @ W + bias.
// 128x128 tile, BK=32, 8 warps (2x4), warp tile 64x32.
// ---------------------------------------------------------------------------
#define GAST 36
#define GBST 136
#define ASTG (128 * GAST)
#define BSTG (32 * GBST)

__device__ __forceinline__ void store_pair(int csel, float* __restrict__ Cext,
                                           int m, int n, float v0, float v1)
{
    if (m >= MROWS) return;
    if (csel <= 2) {
        float* dst = (csel == 0) ? g_q : (csel == 1) ? g_k : g_v;
        if (csel == 0) { v0 = to_tf32(v0 * QSCALE); v1 = to_tf32(v1 * QSCALE); }
        else           { v0 = to_tf32(v0);          v1 = to_tf32(v1); }
        int b = m / SEQ;
        int s = m - b * SEQ;
        int h = n >> 6;
        int d = n & 63;
        *(float2*)&dst[(((size_t)(b * HEADS + h)) * SEQ + s) * HDIM + d] =
            make_float2(v0, v1);
    } else {
        *(float2*)&Cext[(size_t)m * DIM + n] = make_float2(v0, v1);
    }
}

__global__ __launch_bounds__(256, 2) void gemm_tf32(
    const float* __restrict__ B0, const float* __restrict__ B1,
    const float* __restrict__ B2, float* __restrict__ Cext, int mode)
{
    extern __shared__ float smg[];
    float* As = smg;               // [3][ASTG]
    float* Bs = smg + 3 * ASTG;    // [3][BSTG]

    int z = (mode == 1) ? 3 : blockIdx.z;
    const float* A    = (mode == 1) ? g_ctx : g_xr;
    const float* W    = g_wr + (size_t)z * DIM * DIM;
    const float* bias = (mode == 1) ? B0 : (z == 0 ? B0 : (z == 1 ? B1 : B2));
    int csel          = (mode == 1) ? 3 : z;

    int tid = threadIdx.x;
    int wid = tid >> 5, lane = tid & 31;
    int wm = wid & 1, wn = wid >> 1;
    int lr = lane >> 2, lc = lane & 3;
    int m0 = blockIdx.x * 128, n0 = blockIdx.y * 128;

    float c[4][4][4];
#pragma unroll
    for (int mt = 0; mt < 4; mt++)
#pragma unroll
        for (int nt = 0; nt < 4; nt++)
#pragma unroll
            for (int i = 0; i < 4; i++) c[mt][nt][i] = 0.f;

    int arow[4], ak4[4]; bool aval[4];
#pragma unroll
    for (int i = 0; i < 4; i++) {
        int idx = tid + i * 256;
        arow[i] = idx >> 3;
        ak4[i] = (idx & 7) * 4;
        aval[i] = (m0 + arow[i]) < MROWS;
    }
    int brow0 = tid >> 5, bn4 = (tid & 31) * 4;

#define G_ISSUE(T, S)                                                           \
    do {                                                                        \
        int _k0 = (T) * 32;                                                     \
        float* _Asd = As + (S) * ASTG;                                          \
        float* _Bsd = Bs + (S) * BSTG;                                          \
        _Pragma("unroll")                                                       \
        for (int _i = 0; _i < 4; _i++)                                          \
            cp16(_Asd + arow[_i] * GAST + ak4[_i],                              \
                 A + (size_t)(m0 + arow[_i]) * DIM + _k0 + ak4[_i], aval[_i]);  \
        _Pragma("unroll")                                                       \
        for (int _i = 0; _i < 4; _i++)                                          \
            cp16(_Bsd + (brow0 + 8 * _i) * GBST + bn4,                          \
                 W + (size_t)(_k0 + brow0 + 8 * _i) * DIM + n0 + bn4, true);    \
        CP_COMMIT();                                                            \
    } while (0)

    G_ISSUE(0, 0);
    G_ISSUE(1, 1);

    int st = 0;
    for (int t = 0; t < 32; t++) {
        if (t + 2 < 32) CP_WAIT1(); else CP_WAIT0();
        __syncthreads();
        if (t + 2 < 32) {
            int s2 = st + 2; if (s2 >= 3) s2 -= 3;
            G_ISSUE(t + 2, s2);
        }

        const float* Asb = As + st * ASTG;
        const float* Bsb = Bs + st * BSTG;

#pragma unroll
        for (int ks = 0; ks < 4; ks++) {
            int kk = ks * 8;
            unsigned bf[4][2];
#pragma unroll
            for (int nt = 0; nt < 4; nt++) {
                int col = wn * 32 + nt * 8 + lr;
                bf[nt][0] = fu(Bsb[(kk + lc) * GBST + col]);
                bf[nt][1] = fu(Bsb[(kk + lc + 4) * GBST + col]);
            }
#pragma unroll
            for (int mt = 0; mt < 4; mt++) {
                int ar = wm * 64 + mt * 16 + lr;
                unsigned a0 = fu(Asb[ar * GAST + kk + lc]);
                unsigned a1 = fu(Asb[(ar + 8) * GAST + kk + lc]);
                unsigned a2 = fu(Asb[ar * GAST + kk + lc + 4]);
                unsigned a3 = fu(Asb[(ar + 8) * GAST + kk + lc + 4]);
#pragma unroll
                for (int nt = 0; nt < 4; nt++)
                    mma_tf32(c[mt][nt], a0, a1, a2, a3, bf[nt][0], bf[nt][1]);
            }
        }
        if (++st == 3) st = 0;
    }

#pragma unroll
    for (int mt = 0; mt < 4; mt++) {
        int r0 = m0 + wm * 64 + mt * 16 + lr;
        int r1 = r0 + 8;
#pragma unroll
        for (int nt = 0; nt < 4; nt++) {
            int n = n0 + wn * 32 + nt * 8 + lc * 2;
            float b0v = bias[n], b1v = bias[n + 1];
            store_pair(csel, Cext, r0, n, c[mt][nt][0] + b0v, c[mt][nt][1] + b1v);
            store_pair(csel, Cext, r1, n, c[mt][nt][2] + b0v, c[mt][nt][3] + b1v);
        }
    }
}

// ---------------------------------------------------------------------------
// TF32 flash attention v3: 128 q-rows/CTA, 8 warps, warp tile 16x64,
// in-warp softmax. PV uses the permuted-k trick: P C-frags feed the MMA
// A-slots directly (slot (lr,lc) <-> logical k=2lc; slot (lr,lc+4) <-> k=2lc+1)
// and V rows are read in the SAME permuted order (2lc, 2lc+1) -> zero shuffles.
// ---------------------------------------------------------------------------
#define QST 68
#define KST 68
#define VST 68   // (2lc)*68 % 128 = 8lc*16B -> conflict-free for permuted rows
#define NT  ((SEQ + 63) / 64)   // 22

__global__ __launch_bounds__(256, 2) void attn_tf32()
{
    extern __shared__ float sma[];
    float* Qs = sma;                     // [128][68]
    float* Ks = Qs + 128 * QST;          // [2][64][68]
    float* Vs = Ks + 2 * 64 * KST;       // [2][64][68]

    int tid = threadIdx.x;
    int w = tid >> 5, lane = tid & 31;
    int lr = lane >> 2, lc = lane & 3;

    int bh = blockIdx.y;
    int b = bh >> 4;
    int h = bh & 15;
    int q0 = blockIdx.x * 128;

    const float* Qg = g_q + ((size_t)(b * HEADS + h)) * SEQ * HDIM;
    const float* Kg = g_k + ((size_t)(b * HEADS + h)) * SEQ * HDIM;
    const float* Vg = g_v + ((size_t)(b * HEADS + h)) * SEQ * HDIM;

    const float4 z4 = make_float4(0.f, 0.f, 0.f, 0.f);

    // Q tile: 128 rows (already tf32 + pre-scaled by 0.125*log2e)
    for (int e = tid; e < 2048; e += 256) {
        int r = e >> 4;
        int d4 = (e & 15) * 4;
        float4 v = (q0 + r < SEQ) ? *(const float4*)(Qg + (size_t)(q0 + r) * HDIM + d4) : z4;
        *(float4*)&Qs[r * QST + d4] = v;
    }

#define A_ISSUE(T, S)                                                         \
    do {                                                                      \
        int _k0 = (T) * 64;                                                   \
        float* _Kd = Ks + (S) * 64 * KST;                                     \
        float* _Vd = Vs + (S) * 64 * VST;                                     \
        _Pragma("unroll")                                                     \
        for (int _i = 0; _i < 4; _i++) {                                      \
            int _idx = tid + _i * 256;                                        \
            int _r = _idx >> 4;                                               \
            int _d4 = (_idx & 15) * 4;                                        \
            bool _ok = (_k0 + _r) < SEQ;                                      \
            cp16(_Kd + _r * KST + _d4, Kg + (size_t)(_k0 + _r) * HDIM + _d4, _ok); \
            cp16(_Vd + _r * VST + _d4, Vg + (size_t)(_k0 + _r) * HDIM + _d4, _ok); \
        }                                                                     \
        CP_COMMIT();                                                          \
    } while (0)

    float o[8][4];   // O: 16 rows x 64 d-cols per warp
#pragma unroll
    for (int od = 0; od < 8; od++)
#pragma unroll
        for (int i = 0; i < 4; i++) o[od][i] = 0.f;
    float m0v = -INFINITY, m1v = -INFINITY, l0 = 0.f, l1 = 0.f;

    int qr = w * 16 + lr;   // local q row (this warp)

    A_ISSUE(0, 0);

    for (int t = 0; t < NT; t++) {
        CP_WAIT0();
        __syncthreads();
        if (t + 1 < NT) A_ISSUE(t + 1, (t + 1) & 1);

        const float* Ksb = Ks + (t & 1) * 64 * KST;
        const float* Vsb = Vs + (t & 1) * 64 * VST;

        // S(16x64) = Q @ K^T  (full 64 k-cols per warp)
        float s[8][4];
#pragma unroll
        for (int nt = 0; nt < 8; nt++)
#pragma unroll
            for (int i = 0; i < 4; i++) s[nt][i] = 0.f;

#pragma unroll
        for (int ks = 0; ks < 8; ks++) {
            int kk = ks * 8;
            unsigned a0 = fu(Qs[qr * QST + kk + lc]);
            unsigned a1 = fu(Qs[(qr + 8) * QST + kk + lc]);
            unsigned a2 = fu(Qs[qr * QST + kk + lc + 4]);
            unsigned a3 = fu(Qs[(qr + 8) * QST + kk + lc + 4]);
#pragma unroll
            for (int nt = 0; nt < 8; nt++) {
                int krow = nt * 8 + lr;
                unsigned b0 = fu(Ksb[krow * KST + kk + lc]);
                unsigned b1 = fu(Ksb[krow * KST + kk + lc + 4]);
                mma_tf32(s[nt], a0, a1, a2, a3, b0, b1);
            }
        }

        // Mask only on the final partial tile
        if (t == NT - 1) {
#pragma unroll
            for (int nt = 0; nt < 8; nt++)
#pragma unroll
                for (int e = 0; e < 2; e++) {
                    int col = t * 64 + nt * 8 + 2 * lc + e;
                    if (col >= SEQ) { s[nt][e] = -INFINITY; s[nt][2 + e] = -INFINITY; }
                }
        }

        // In-warp row max (quad shuffles complete the 64-col row)
        float rmax0 = -INFINITY, rmax1 = -INFINITY;
#pragma unroll
        for (int nt = 0; nt < 8; nt++) {
            rmax0 = fmaxf(rmax0, fmaxf(s[nt][0], s[nt][1]));
            rmax1 = fmaxf(rmax1, fmaxf(s[nt][2], s[nt][3]));
        }
        rmax0 = fmaxf(rmax0, __shfl_xor_sync(0xffffffffu, rmax0, 1));
        rmax0 = fmaxf(rmax0, __shfl_xor_sync(0xffffffffu, rmax0, 2));
        rmax1 = fmaxf(rmax1, __shfl_xor_sync(0xffffffffu, rmax1, 1));
        rmax1 = fmaxf(rmax1, __shfl_xor_sync(0xffffffffu, rmax1, 2));

        float mn0 = fmaxf(m0v, rmax0);
        float mn1 = fmaxf(m1v, rmax1);
        float alpha0 = ex2(m0v - mn0);
        float alpha1 = ex2(m1v - mn1);
        m0v = mn0; m1v = mn1;

        float sum0 = 0.f, sum1 = 0.f;
#pragma unroll
        for (int nt = 0; nt < 8; nt++) {
#pragma unroll
            for (int e = 0; e < 2; e++) {
                float p0 = ex2(s[nt][e] - mn0);
                float p1 = ex2(s[nt][2 + e] - mn1);
                sum0 += p0; sum1 += p1;
                s[nt][e] = to_tf32(p0);
                s[nt][2 + e] = to_tf32(p1);
            }
        }
        sum0 += __shfl_xor_sync(0xffffffffu, sum0, 1);
        sum0 += __shfl_xor_sync(0xffffffffu, sum0, 2);
        sum1 += __shfl_xor_sync(0xffffffffu, sum1, 1);
        sum1 += __shfl_xor_sync(0xffffffffu, sum1, 2);
        l0 = l0 * alpha0 + sum0;
        l1 = l1 * alpha1 + sum1;

#pragma unroll
        for (int od = 0; od < 8; od++) {
            o[od][0] *= alpha0; o[od][1] *= alpha0;
            o[od][2] *= alpha1; o[od][3] *= alpha1;
        }

        // PV, permuted-k: A-slots direct from C-frags (a0=c0, a1=c2, a2=c1,
        // a3=c3); V rows read at logical k = 2lc, 2lc+1 (same permutation).
#pragma unroll
        for (int kb = 0; kb < 8; kb++) {
            unsigned a0 = fu(s[kb][0]);
            unsigned a1 = fu(s[kb][2]);
            unsigned a2 = fu(s[kb][1]);
            unsigned a3 = fu(s[kb][3]);
            int vr0 = kb * 8 + 2 * lc;       // logical k for slot lc
            int vr1 = vr0 + 1;               // logical k for slot lc+4
#pragma unroll
            for (int od = 0; od < 8; od++) {
                int col = od * 8 + lr;
                unsigned b0 = fu(Vsb[vr0 * VST + col]);
                unsigned b1 = fu(Vsb[vr1 * VST + col]);
                mma_tf32(o[od], a0, a1, a2, a3, b0, b1);
            }
        }
    }

    // Epilogue: normalize, write [B,S,D] (tf32 for the O-proj cp.async path)
    float inv0 = 1.f / l0;
    float inv1 = 1.f / l1;
    int r0 = q0 + qr, r1 = r0 + 8;
#pragma unroll
    for (int od = 0; od < 8; od++) {
        int col = h * HDIM + od * 8 + lc * 2;
        if (r0 < SEQ)
            *(float2*)&g_ctx[((size_t)(b * SEQ + r0)) * DIM + col] =
                make_float2(to_tf32(o[od][0] * inv0), to_tf32(o[od][1] * inv0));
        if (r1 < SEQ)
            *(float2*)&g_ctx[((size_t)(b * SEQ + r1)) * DIM + col] =
                make_float2(to_tf32(o[od][2] * inv1), to_tf32(o[od][3] * inv1));
    }
}

// ---------------------------------------------------------------------------
extern "C" void kernel_launch(void* const* d_in, const int* in_sizes, int n_in,
                              void* d_out, int out_size)
{
    const float* x  = (const float*)d_in[0];
    const float* Wq = (const float*)d_in[1];
    const float* bq = (const float*)d_in[2];
    const float* Wk = (const float*)d_in[3];
    const float* bk = (const float*)d_in[4];
    const float* Wv = (const float*)d_in[5];
    const float* bv = (const float*)d_in[6];
    const float* Wo = (const float*)d_in[7];
    const float* bo = (const float*)d_in[8];
    float* out = (float*)d_out;

    round_x<<<(MROWS * DIM / 4 + 255) / 256, 256>>>(x);
    round_w<<<(4 * DIM * DIM / 4 + 255) / 256, 256>>>(Wq, Wk, Wv, Wo);

    int gsm = (3 * ASTG + 3 * BSTG) * sizeof(float);   // 107520
    cudaFuncSetAttribute(gemm_tf32, cudaFuncAttributeMaxDynamicSharedMemorySize, gsm);

    dim3 qkvGrid((MROWS + 127) / 128, DIM / 128, 3);  // 86 x 8 x 3
    gemm_tf32<<<qkvGrid, 256, gsm>>>(bq, bk, bv, nullptr, 0);

    int asm_ = (128 * QST + 2 * 64 * KST + 2 * 64 * VST) * sizeof(float);  // 104448
    cudaFuncSetAttribute(attn_tf32, cudaFuncAttributeMaxDynamicSharedMemorySize, asm_);
    dim3 attnGrid((SEQ + 127) / 128, BATCH * HEADS);  // 11 x 128
    attn_tf32<<<attnGrid, 256, asm_>>>();

    dim3 oGrid((MROWS + 127) / 128, DIM / 128, 1);
    gemm_tf32<<<oGrid, 256, gsm>>>(bo, nullptr, nullptr, out, 1);
}

// round 13
// speedup vs baseline: 1.5473x; 1.5473x over previous
#include <cuda_runtime.h>
#include <math.h>
#include <stdint.h>

#define BATCH 8
#define SEQ 1370
#define DIM 1024
#define HEADS 16
#define HDIM 64
#define MROWS (BATCH * SEQ)   // 10960

// Q pre-scale: 1/sqrt(64) * log2(e)  (softmax computed in base-2 domain)
#define QSCALE 0.18033688011112042f

// Scratch (allocation-free: device globals)
__device__ __align__(256) float g_q[BATCH * HEADS * SEQ * HDIM];   // [B,H,S,Dh] tf32, pre-scaled
__device__ __align__(256) float g_k[BATCH * HEADS * SEQ * HDIM];
__device__ __align__(256) float g_v[BATCH * HEADS * SEQ * HDIM];
__device__ __align__(256) float g_ctx[BATCH * SEQ * DIM];          // [B,S,D] tf32
__device__ __align__(256) float g_xr[MROWS * DIM];                 // x rounded to tf32
__device__ __align__(256) float g_wr[4 * DIM * DIM];               // Wq,Wk,Wv,Wo rounded [k][n]

__device__ __forceinline__ float to_tf32(float x) {
    float r; asm("cvt.rna.tf32.f32 %0, %1;" : "=f"(r) : "f"(x)); return r;
}
__device__ __forceinline__ unsigned fu(float x) { return __float_as_uint(x); }
__device__ __forceinline__ float ex2(float x) {
    float r; asm("ex2.approx.f32 %0, %1;" : "=f"(r) : "f"(x)); return r;
}

__device__ __forceinline__ void mma_tf32(float c[4],
    unsigned a0, unsigned a1, unsigned a2, unsigned a3,
    unsigned b0, unsigned b1)
{
    asm volatile(
        "mma.sync.aligned.m16n8k8.row.col.f32.tf32.tf32.f32 "
        "{%0,%1,%2,%3}, {%4,%5,%6,%7}, {%8,%9}, {%0,%1,%2,%3};"
        : "+f"(c[0]), "+f"(c[1]), "+f"(c[2]), "+f"(c[3])
        : "r"(a0), "r"(a1), "r"(a2), "r"(a3), "r"(b0), "r"(b1));
}

// ---- cp.async helpers ----
__device__ __forceinline__ void cp16(void* smem_dst, const void* gsrc, bool pred) {
    unsigned d = (unsigned)__cvta_generic_to_shared(smem_dst);
    int sz = pred ? 16 : 0;
    asm volatile("cp.async.cg.shared.global [%0], [%1], 16, %2;\n"
                 :: "r"(d), "l"(gsrc), "r"(sz));
}
#define CP_COMMIT() asm volatile("cp.async.commit_group;\n")
#define CP_WAIT0()  asm volatile("cp.async.wait_group 0;\n" ::: "memory")
#define CP_WAIT1()  asm volatile("cp.async.wait_group 1;\n" ::: "memory")

// ---------------------------------------------------------------------------
// Pre-rounding passes
// ---------------------------------------------------------------------------
__global__ __launch_bounds__(256) void round_x(const float* __restrict__ x)
{
    int i = blockIdx.x * blockDim.x + threadIdx.x;
    if (i >= MROWS * DIM / 4) return;
    float4 v = ((const float4*)x)[i];
    ((float4*)g_xr)[i] = make_float4(to_tf32(v.x), to_tf32(v.y), to_tf32(v.z), to_tf32(v.w));
}

__global__ __launch_bounds__(256) void round_w(
    const float* __restrict__ wq, const float* __restrict__ wk,
    const float* __restrict__ wv, const float* __restrict__ wo)
{
    int i = blockIdx.x * blockDim.x + threadIdx.x;
    int w = i >> 18;
    int j = i & 262143;
    const float* s = (w == 0) ? wq : (w == 1) ? wk : (w == 2) ? wv : wo;
    float4 v = ((const float4*)s)[j];
    ((float4*)g_wr)[i] = make_float4(to_tf32(v.x), to_tf32(v.y), to_tf32(v.z), to_tf32(v.w));
}

// ---------------------------------------------------------------------------
// TF32 GEMM, 3-stage cp.async pipeline (R8 proven). C = A @ W + bias.
// 128x128 tile, BK=32, 8 warps (2x4), warp tile 64x32.
// ---------------------------------------------------------------------------
#define GAST 36
#define GBST 136
#define ASTG (128 * GAST)
#define BSTG (32 * GBST)

__device__ __forceinline__ void store_pair(int csel, float* __restrict__ Cext,
                                           int m, int n, float v0, float v1)
{
    if (m >= MROWS) return;
    if (csel <= 2) {
        float* dst = (csel == 0) ? g_q : (csel == 1) ? g_k : g_v;
        if (csel == 0) { v0 = to_tf32(v0 * QSCALE); v1 = to_tf32(v1 * QSCALE); }
        else           { v0 = to_tf32(v0);          v1 = to_tf32(v1); }
        int b = m / SEQ;
        int s = m - b * SEQ;
        int h = n >> 6;
        int d = n & 63;
        *(float2*)&dst[(((size_t)(b * HEADS + h)) * SEQ + s) * HDIM + d] =
            make_float2(v0, v1);
    } else {
        *(float2*)&Cext[(size_t)m * DIM + n] = make_float2(v0, v1);
    }
}

__global__ __launch_bounds__(256, 2) void gemm_tf32(
    const float* __restrict__ B0, const float* __restrict__ B1,
    const float* __restrict__ B2, float* __restrict__ Cext, int mode)
{
    extern __shared__ float smg[];
    float* As = smg;               // [3][ASTG]
    float* Bs = smg + 3 * ASTG;    // [3][BSTG]

    int z = (mode == 1) ? 3 : blockIdx.z;
    const float* A    = (mode == 1) ? g_ctx : g_xr;
    const float* W    = g_wr + (size_t)z * DIM * DIM;
    const float* bias = (mode == 1) ? B0 : (z == 0 ? B0 : (z == 1 ? B1 : B2));
    int csel          = (mode == 1) ? 3 : z;

    int tid = threadIdx.x;
    int wid = tid >> 5, lane = tid & 31;
    int wm = wid & 1, wn = wid >> 1;
    int lr = lane >> 2, lc = lane & 3;
    int m0 = blockIdx.x * 128, n0 = blockIdx.y * 128;

    float c[4][4][4];
#pragma unroll
    for (int mt = 0; mt < 4; mt++)
#pragma unroll
        for (int nt = 0; nt < 4; nt++)
#pragma unroll
            for (int i = 0; i < 4; i++) c[mt][nt][i] = 0.f;

    int arow[4], ak4[4]; bool aval[4];
#pragma unroll
    for (int i = 0; i < 4; i++) {
        int idx = tid + i * 256;
        arow[i] = idx >> 3;
        ak4[i] = (idx & 7) * 4;
        aval[i] = (m0 + arow[i]) < MROWS;
    }
    int brow0 = tid >> 5, bn4 = (tid & 31) * 4;

#define G_ISSUE(T, S)                                                           \
    do {                                                                        \
        int _k0 = (T) * 32;                                                     \
        float* _Asd = As + (S) * ASTG;                                          \
        float* _Bsd = Bs + (S) * BSTG;                                          \
        _Pragma("unroll")                                                       \
        for (int _i = 0; _i < 4; _i++)                                          \
            cp16(_Asd + arow[_i] * GAST + ak4[_i],                              \
                 A + (size_t)(m0 + arow[_i]) * DIM + _k0 + ak4[_i], aval[_i]);  \
        _Pragma("unroll")                                                       \
        for (int _i = 0; _i < 4; _i++)                                          \
            cp16(_Bsd + (brow0 + 8 * _i) * GBST + bn4,                          \
                 W + (size_t)(_k0 + brow0 + 8 * _i) * DIM + n0 + bn4, true);    \
        CP_COMMIT();                                                            \
    } while (0)

    G_ISSUE(0, 0);
    G_ISSUE(1, 1);

    int st = 0;
    for (int t = 0; t < 32; t++) {
        if (t + 2 < 32) CP_WAIT1(); else CP_WAIT0();
        __syncthreads();
        if (t + 2 < 32) {
            int s2 = st + 2; if (s2 >= 3) s2 -= 3;
            G_ISSUE(t + 2, s2);
        }

        const float* Asb = As + st * ASTG;
        const float* Bsb = Bs + st * BSTG;

#pragma unroll
        for (int ks = 0; ks < 4; ks++) {
            int kk = ks * 8;
            unsigned bf[4][2];
#pragma unroll
            for (int nt = 0; nt < 4; nt++) {
                int col = wn * 32 + nt * 8 + lr;
                bf[nt][0] = fu(Bsb[(kk + lc) * GBST + col]);
                bf[nt][1] = fu(Bsb[(kk + lc + 4) * GBST + col]);
            }
#pragma unroll
            for (int mt = 0; mt < 4; mt++) {
                int ar = wm * 64 + mt * 16 + lr;
                unsigned a0 = fu(Asb[ar * GAST + kk + lc]);
                unsigned a1 = fu(Asb[(ar + 8) * GAST + kk + lc]);
                unsigned a2 = fu(Asb[ar * GAST + kk + lc + 4]);
                unsigned a3 = fu(Asb[(ar + 8) * GAST + kk + lc + 4]);
#pragma unroll
                for (int nt = 0; nt < 4; nt++)
                    mma_tf32(c[mt][nt], a0, a1, a2, a3, bf[nt][0], bf[nt][1]);
            }
        }
        if (++st == 3) st = 0;
    }

#pragma unroll
    for (int mt = 0; mt < 4; mt++) {
        int r0 = m0 + wm * 64 + mt * 16 + lr;
        int r1 = r0 + 8;
#pragma unroll
        for (int nt = 0; nt < 4; nt++) {
            int n = n0 + wn * 32 + nt * 8 + lc * 2;
            float b0v = bias[n], b1v = bias[n + 1];
            store_pair(csel, Cext, r0, n, c[mt][nt][0] + b0v, c[mt][nt][1] + b1v);
            store_pair(csel, Cext, r1, n, c[mt][nt][2] + b0v, c[mt][nt][3] + b1v);
        }
    }
}

// ---------------------------------------------------------------------------
// TF32 flash attention v3.1: 128 q-rows/CTA, 8 warps, warp tile 16x64,
// in-warp softmax, permuted-k PV (zero shuffles). Q tile now loaded via
// cp.async, overlapped with the first K/V fetch (no serial LDG prologue).
// ---------------------------------------------------------------------------
#define QST 68
#define KST 68
#define VST 68   // (2lc)*68: bank = 8lc+8od+lr -> conflict-free permuted rows
#define NT  ((SEQ + 63) / 64)   // 22

__global__ __launch_bounds__(256, 2) void attn_tf32()
{
    extern __shared__ float sma[];
    float* Qs = sma;                     // [128][68]
    float* Ks = Qs + 128 * QST;          // [2][64][68]
    float* Vs = Ks + 2 * 64 * KST;       // [2][64][68]

    int tid = threadIdx.x;
    int w = tid >> 5, lane = tid & 31;
    int lr = lane >> 2, lc = lane & 3;

    int bh = blockIdx.y;
    int b = bh >> 4;
    int h = bh & 15;
    int q0 = blockIdx.x * 128;

    const float* Qg = g_q + ((size_t)(b * HEADS + h)) * SEQ * HDIM;
    const float* Kg = g_k + ((size_t)(b * HEADS + h)) * SEQ * HDIM;
    const float* Vg = g_v + ((size_t)(b * HEADS + h)) * SEQ * HDIM;

    // Q tile via cp.async (folded into the first commit group below)
    for (int e = tid; e < 2048; e += 256) {
        int r = e >> 4;
        int d4 = (e & 15) * 4;
        cp16(&Qs[r * QST + d4], Qg + (size_t)(q0 + r) * HDIM + d4, (q0 + r) < SEQ);
    }

#define A_ISSUE(T, S)                                                         \
    do {                                                                      \
        int _k0 = (T) * 64;                                                   \
        float* _Kd = Ks + (S) * 64 * KST;                                     \
        float* _Vd = Vs + (S) * 64 * VST;                                     \
        _Pragma("unroll")                                                     \
        for (int _i = 0; _i < 4; _i++) {                                      \
            int _idx = tid + _i * 256;                                        \
            int _r = _idx >> 4;                                               \
            int _d4 = (_idx & 15) * 4;                                        \
            bool _ok = (_k0 + _r) < SEQ;                                      \
            cp16(_Kd + _r * KST + _d4, Kg + (size_t)(_k0 + _r) * HDIM + _d4, _ok); \
            cp16(_Vd + _r * VST + _d4, Vg + (size_t)(_k0 + _r) * HDIM + _d4, _ok); \
        }                                                                     \
        CP_COMMIT();                                                          \
    } while (0)

    float o[8][4];   // O: 16 rows x 64 d-cols per warp
#pragma unroll
    for (int od = 0; od < 8; od++)
#pragma unroll
        for (int i = 0; i < 4; i++) o[od][i] = 0.f;
    float m0v = -INFINITY, m1v = -INFINITY, l0 = 0.f, l1 = 0.f;

    int qr = w * 16 + lr;   // local q row (this warp)

    A_ISSUE(0, 0);   // Q copies + first K/V tile commit as group 0

    for (int t = 0; t < NT; t++) {
        CP_WAIT0();
        __syncthreads();
        if (t + 1 < NT) A_ISSUE(t + 1, (t + 1) & 1);

        const float* Ksb = Ks + (t & 1) * 64 * KST;
        const float* Vsb = Vs + (t & 1) * 64 * VST;

        // S(16x64) = Q @ K^T  (full 64 k-cols per warp)
        float s[8][4];
#pragma unroll
        for (int nt = 0; nt < 8; nt++)
#pragma unroll
            for (int i = 0; i < 4; i++) s[nt][i] = 0.f;

#pragma unroll
        for (int ks = 0; ks < 8; ks++) {
            int kk = ks * 8;
            unsigned a0 = fu(Qs[qr * QST + kk + lc]);
            unsigned a1 = fu(Qs[(qr + 8) * QST + kk + lc]);
            unsigned a2 = fu(Qs[qr * QST + kk + lc + 4]);
            unsigned a3 = fu(Qs[(qr + 8) * QST + kk + lc + 4]);
#pragma unroll
            for (int nt = 0; nt < 8; nt++) {
                int krow = nt * 8 + lr;
                unsigned b0 = fu(Ksb[krow * KST + kk + lc]);
                unsigned b1 = fu(Ksb[krow * KST + kk + lc + 4]);
                mma_tf32(s[nt], a0, a1, a2, a3, b0, b1);
            }
        }

        // Mask only on the final partial tile
        if (t == NT - 1) {
#pragma unroll
            for (int nt = 0; nt < 8; nt++)
#pragma unroll
                for (int e = 0; e < 2; e++) {
                    int col = t * 64 + nt * 8 + 2 * lc + e;
                    if (col >= SEQ) { s[nt][e] = -INFINITY; s[nt][2 + e] = -INFINITY; }
                }
        }

        // In-warp row max (quad shuffles complete the 64-col row)
        float rmax0 = -INFINITY, rmax1 = -INFINITY;
#pragma unroll
        for (int nt = 0; nt < 8; nt++) {
            rmax0 = fmaxf(rmax0, fmaxf(s[nt][0], s[nt][1]));
            rmax1 = fmaxf(rmax1, fmaxf(s[nt][2], s[nt][3]));
        }
        rmax0 = fmaxf(rmax0, __shfl_xor_sync(0xffffffffu, rmax0, 1));
        rmax0 = fmaxf(rmax0, __shfl_xor_sync(0xffffffffu, rmax0, 2));
        rmax1 = fmaxf(rmax1, __shfl_xor_sync(0xffffffffu, rmax1, 1));
        rmax1 = fmaxf(rmax1, __shfl_xor_sync(0xffffffffu, rmax1, 2));

        float mn0 = fmaxf(m0v, rmax0);
        float mn1 = fmaxf(m1v, rmax1);
        float alpha0 = ex2(m0v - mn0);
        float alpha1 = ex2(m1v - mn1);
        m0v = mn0; m1v = mn1;

        float sum0 = 0.f, sum1 = 0.f;
#pragma unroll
        for (int nt = 0; nt < 8; nt++) {
#pragma unroll
            for (int e = 0; e < 2; e++) {
                float p0 = ex2(s[nt][e] - mn0);
                float p1 = ex2(s[nt][2 + e] - mn1);
                sum0 += p0; sum1 += p1;
                s[nt][e] = to_tf32(p0);
                s[nt][2 + e] = to_tf32(p1);
            }
        }
        sum0 += __shfl_xor_sync(0xffffffffu, sum0, 1);
        sum0 += __shfl_xor_sync(0xffffffffu, sum0, 2);
        sum1 += __shfl_xor_sync(0xffffffffu, sum1, 1);
        sum1 += __shfl_xor_sync(0xffffffffu, sum1, 2);
        l0 = l0 * alpha0 + sum0;
        l1 = l1 * alpha1 + sum1;

#pragma unroll
        for (int od = 0; od < 8; od++) {
            o[od][0] *= alpha0; o[od][1] *= alpha0;
            o[od][2] *= alpha1; o[od][3] *= alpha1;
        }

        // PV, permuted-k: A-slots direct from C-frags (a0=c0, a1=c2, a2=c1,
        // a3=c3); V rows read at logical k = 2lc, 2lc+1 (same permutation).
#pragma unroll
        for (int kb = 0; kb < 8; kb++) {
            unsigned a0 = fu(s[kb][0]);
            unsigned a1 = fu(s[kb][2]);
            unsigned a2 = fu(s[kb][1]);
            unsigned a3 = fu(s[kb][3]);
            int vr0 = kb * 8 + 2 * lc;       // logical k for slot lc
            int vr1 = vr0 + 1;               // logical k for slot lc+4
#pragma unroll
            for (int od = 0; od < 8; od++) {
                int col = od * 8 + lr;
                unsigned b0 = fu(Vsb[vr0 * VST + col]);
                unsigned b1 = fu(Vsb[vr1 * VST + col]);
                mma_tf32(o[od], a0, a1, a2, a3, b0, b1);
            }
        }
    }

    // Epilogue: normalize, write [B,S,D] (tf32 for the O-proj cp.async path)
    float inv0 = 1.f / l0;
    float inv1 = 1.f / l1;
    int r0 = q0 + qr, r1 = r0 + 8;
#pragma unroll
    for (int od = 0; od < 8; od++) {
        int col = h * HDIM + od * 8 + lc * 2;
        if (r0 < SEQ)
            *(float2*)&g_ctx[((size_t)(b * SEQ + r0)) * DIM + col] =
                make_float2(to_tf32(o[od][0] * inv0), to_tf32(o[od][1] * inv0));
        if (r1 < SEQ)
            *(float2*)&g_ctx[((size_t)(b * SEQ + r1)) * DIM + col] =
                make_float2(to_tf32(o[od][2] * inv1), to_tf32(o[od][3] * inv1));
    }
}

// ---------------------------------------------------------------------------
extern "C" void kernel_launch(void* const* d_in, const int* in_sizes, int n_in,
                              void* d_out, int out_size)
{
    const float* x  = (const float*)d_in[0];
    const float* Wq = (const float*)d_in[1];
    const float* bq = (const float*)d_in[2];
    const float* Wk = (const float*)d_in[3];
    const float* bk = (const float*)d_in[4];
    const float* Wv = (const float*)d_in[5];
    const float* bv = (const float*)d_in[6];
    const float* Wo = (const float*)d_in[7];
    const float* bo = (const float*)d_in[8];
    float* out = (float*)d_out;

    round_x<<<(MROWS * DIM / 4 + 255) / 256, 256>>>(x);
    round_w<<<(4 * DIM * DIM / 4 + 255) / 256, 256>>>(Wq, Wk, Wv, Wo);

    int gsm = (3 * ASTG + 3 * BSTG) * sizeof(float);   // 107520
    cudaFuncSetAttribute(gemm_tf32, cudaFuncAttributeMaxDynamicSharedMemorySize, gsm);

    dim3 qkvGrid((MROWS + 127) / 128, DIM / 128, 3);  // 86 x 8 x 3
    gemm_tf32<<<qkvGrid, 256, gsm>>>(bq, bk, bv, nullptr, 0);

    int asm_ = (128 * QST + 2 * 64 * KST + 2 * 64 * VST) * sizeof(float);  // 104448
    cudaFuncSetAttribute(attn_tf32, cudaFuncAttributeMaxDynamicSharedMemorySize, asm_);
    dim3 attnGrid((SEQ + 127) / 128, BATCH * HEADS);  // 11 x 128
    attn_tf32<<<attnGrid, 256, asm_>>>();

    dim3 oGrid((MROWS + 127) / 128, DIM / 128, 1);
    gemm_tf32<<<oGrid, 256, gsm>>>(bo, nullptr, nullptr, out, 1);
}

// round 14
// speedup vs baseline: 2.4033x; 1.5532x over previous
#include <cuda_runtime.h>
#include <cuda_fp16.h>
#include <math.h>
#include <stdint.h>

#define BATCH 8
#define SEQ 1370
#define SEQP 1376             // padded seq for 16B-aligned transposed-V rows
#define DIM 1024
#define HEADS 16
#define HDIM 64
#define MROWS (BATCH * SEQ)   // 10960

// Q pre-scale: 1/sqrt(64) * log2(e)  (softmax computed in base-2 domain)
#define QSCALE 0.18033688011112042f

// Scratch (allocation-free: device globals) — all fp16 operands
__device__ __align__(256) __half g_qh[BATCH * HEADS * SEQ * HDIM];   // [B,H,S,Dh] pre-scaled
__device__ __align__(256) __half g_kh[BATCH * HEADS * SEQ * HDIM];   // [B,H,S,Dh]
__device__ __align__(256) __half g_vT[BATCH * HEADS * HDIM * SEQP];  // [B,H,Dh,Sp] transposed
__device__ __align__(256) __half g_ch[BATCH * SEQ * DIM];            // [B,S,D]
__device__ __align__(256) __half g_xh[MROWS * DIM];                  // x rounded
__device__ __align__(256) __half g_wh[4 * DIM * DIM];                // W^T: [z][n][k]

__device__ __forceinline__ float ex2(float x) {
    float r; asm("ex2.approx.f32 %0, %1;" : "=f"(r) : "f"(x)); return r;
}
__device__ __forceinline__ unsigned pack_h2(float lo, float hi) {
    __half2 h = __floats2half2_rn(lo, hi);
    return *(unsigned*)&h;
}
__device__ __forceinline__ unsigned ldh2(const __half* p) {
    return *(const unsigned*)p;
}

__device__ __forceinline__ void mma_f16(float c[4],
    unsigned a0, unsigned a1, unsigned a2, unsigned a3,
    unsigned b0, unsigned b1)
{
    asm volatile(
        "mma.sync.aligned.m16n8k16.row.col.f32.f16.f16.f32 "
        "{%0,%1,%2,%3}, {%4,%5,%6,%7}, {%8,%9}, {%0,%1,%2,%3};"
        : "+f"(c[0]), "+f"(c[1]), "+f"(c[2]), "+f"(c[3])
        : "r"(a0), "r"(a1), "r"(a2), "r"(a3), "r"(b0), "r"(b1));
}

// ---- cp.async helpers ----
__device__ __forceinline__ void cp16(void* smem_dst, const void* gsrc, bool pred) {
    unsigned d = (unsigned)__cvta_generic_to_shared(smem_dst);
    int sz = pred ? 16 : 0;
    asm volatile("cp.async.cg.shared.global [%0], [%1], 16, %2;\n"
                 :: "r"(d), "l"(gsrc), "r"(sz));
}
#define CP_COMMIT() asm volatile("cp.async.commit_group;\n")
#define CP_WAIT0()  asm volatile("cp.async.wait_group 0;\n" ::: "memory")
#define CP_WAIT1()  asm volatile("cp.async.wait_group 1;\n" ::: "memory")

// ---------------------------------------------------------------------------
// Pre-rounding passes
// ---------------------------------------------------------------------------
__global__ __launch_bounds__(256) void round_x(const float* __restrict__ x)
{
    int i = blockIdx.x * blockDim.x + threadIdx.x;
    if (i >= MROWS * DIM / 4) return;
    float4 v = ((const float4*)x)[i];
    ((__half2*)g_xh)[2 * i]     = __floats2half2_rn(v.x, v.y);
    ((__half2*)g_xh)[2 * i + 1] = __floats2half2_rn(v.z, v.w);
}

// Transpose + round: g_wh[z][n][k] = half(W_z[k][n])
__global__ __launch_bounds__(256) void round_wT(
    const float* __restrict__ wq, const float* __restrict__ wk,
    const float* __restrict__ wv, const float* __restrict__ wo)
{
    __shared__ float t[32][33];
    int z = blockIdx.z;
    const float* W = (z == 0) ? wq : (z == 1) ? wk : (z == 2) ? wv : wo;
    int k0 = blockIdx.x * 32, n0 = blockIdx.y * 32;
    int tx = threadIdx.x & 31, ty = threadIdx.x >> 5;   // 32 x 8
#pragma unroll
    for (int i = 0; i < 4; i++)
        t[ty + 8 * i][tx] = W[(size_t)(k0 + ty + 8 * i) * DIM + n0 + tx];
    __syncthreads();
    __half* dst = g_wh + (size_t)z * DIM * DIM;
#pragma unroll
    for (int i = 0; i < 4; i++)
        dst[(size_t)(n0 + ty + 8 * i) * DIM + k0 + tx] = __float2half_rn(t[tx][ty + 8 * i]);
}

// Zero the transposed-V pad columns [SEQ, SEQP)
__global__ __launch_bounds__(256) void zero_vpad()
{
    int i = blockIdx.x * blockDim.x + threadIdx.x;
    int total = BATCH * HEADS * HDIM * (SEQP - SEQ);
    if (i >= total) return;
    int row = i / (SEQP - SEQ);
    int off = i % (SEQP - SEQ);
    g_vT[(size_t)row * SEQP + SEQ + off] = __float2half_rn(0.f);
}

// ---------------------------------------------------------------------------
// FP16 GEMM, 3-stage cp.async, m16n8k16. C = A @ W + bias (fp32 accum).
// 128x128 tile, BK=32, 8 warps (2x4), warp tile 64x32.
// mode 0: fused QKV (z selects); mode 1: out proj.
// ---------------------------------------------------------------------------
#define HAST 40                 // smem row stride in halves (BK32 + 8)
#define HASTG (128 * HAST)      // 5120 halves / stage

__device__ __forceinline__ void store_pair(int csel, float* __restrict__ Cext,
                                           int m, int n, float v0, float v1)
{
    if (m >= MROWS) return;
    int b = m / SEQ;
    int s = m - b * SEQ;
    if (csel == 0) {
        int h = n >> 6, d = n & 63;
        *(__half2*)&g_qh[(((size_t)(b * HEADS + h)) * SEQ + s) * HDIM + d] =
            __floats2half2_rn(v0 * QSCALE, v1 * QSCALE);
    } else if (csel == 1) {
        int h = n >> 6, d = n & 63;
        *(__half2*)&g_kh[(((size_t)(b * HEADS + h)) * SEQ + s) * HDIM + d] =
            __floats2half2_rn(v0, v1);
    } else if (csel == 2) {
        int h = n >> 6, d = n & 63;
        size_t base = ((size_t)(b * HEADS + h)) * HDIM;
        g_vT[(base + d) * SEQP + s]     = __float2half_rn(v0);
        g_vT[(base + d + 1) * SEQP + s] = __float2half_rn(v1);
    } else {
        *(float2*)&Cext[(size_t)m * DIM + n] = make_float2(v0, v1);
    }
}

__global__ __launch_bounds__(256, 2) void gemm_f16(
    const float* __restrict__ B0, const float* __restrict__ B1,
    const float* __restrict__ B2, float* __restrict__ Cext, int mode)
{
    extern __shared__ __half smh[];
    __half* As = smh;                 // [3][128*40]
    __half* Bs = smh + 3 * HASTG;     // [3][128*40]

    int z = (mode == 1) ? 3 : blockIdx.z;
    const __half* A    = (mode == 1) ? g_ch : g_xh;
    const __half* W    = g_wh + (size_t)z * DIM * DIM;   // [n][k]
    const float* bias  = (mode == 1) ? B0 : (z == 0 ? B0 : (z == 1 ? B1 : B2));
    int csel           = (mode == 1) ? 3 : z;

    int tid = threadIdx.x;
    int wid = tid >> 5, lane = tid & 31;
    int wm = wid & 1, wn = wid >> 1;
    int lr = lane >> 2, lc = lane & 3;
    int m0 = blockIdx.x * 128, n0 = blockIdx.y * 128;

    float c[4][4][4];
#pragma unroll
    for (int mt = 0; mt < 4; mt++)
#pragma unroll
        for (int nt = 0; nt < 4; nt++)
#pragma unroll
            for (int i = 0; i < 4; i++) c[mt][nt][i] = 0.f;

    // Loaders: 2 cp16/thread for A, 2 for B (per stage of 128x32 halves)
    int lrow[2], lc8[2];
    bool aval[2];
#pragma unroll
    for (int i = 0; i < 2; i++) {
        int idx = tid + i * 256;
        lrow[i] = idx >> 2;          // 0..127
        lc8[i] = (idx & 3) * 8;      // halves offset 0,8,16,24
        aval[i] = (m0 + lrow[i]) < MROWS;
    }

#define G_ISSUE(T, S)                                                            \
    do {                                                                         \
        int _k0 = (T) * 32;                                                      \
        __half* _Asd = As + (S) * HASTG;                                         \
        __half* _Bsd = Bs + (S) * HASTG;                                         \
        _Pragma("unroll")                                                        \
        for (int _i = 0; _i < 2; _i++) {                                         \
            cp16(_Asd + lrow[_i] * HAST + lc8[_i],                               \
                 A + (size_t)(m0 + lrow[_i]) * DIM + _k0 + lc8[_i], aval[_i]);   \
            cp16(_Bsd + lrow[_i] * HAST + lc8[_i],                               \
                 W + (size_t)(n0 + lrow[_i]) * DIM + _k0 + lc8[_i], true);       \
        }                                                                        \
        CP_COMMIT();                                                             \
    } while (0)

    G_ISSUE(0, 0);
    G_ISSUE(1, 1);

    int st = 0;
    for (int t = 0; t < 32; t++) {
        if (t + 2 < 32) CP_WAIT1(); else CP_WAIT0();
        __syncthreads();
        if (t + 2 < 32) {
            int s2 = st + 2; if (s2 >= 3) s2 -= 3;
            G_ISSUE(t + 2, s2);
        }

        const __half* Asb = As + st * HASTG;
        const __half* Bsb = Bs + st * HASTG;

#pragma unroll
        for (int ks = 0; ks < 2; ks++) {
            int kk = ks * 16;
            unsigned bf[4][2];
#pragma unroll
            for (int nt = 0; nt < 4; nt++) {
                int col = wn * 32 + nt * 8 + lr;
                bf[nt][0] = ldh2(Bsb + col * HAST + kk + 2 * lc);
                bf[nt][1] = ldh2(Bsb + col * HAST + kk + 2 * lc + 8);
            }
#pragma unroll
            for (int mt = 0; mt < 4; mt++) {
                int ar = wm * 64 + mt * 16 + lr;
                unsigned a0 = ldh2(Asb + ar * HAST + kk + 2 * lc);
                unsigned a1 = ldh2(Asb + (ar + 8) * HAST + kk + 2 * lc);
                unsigned a2 = ldh2(Asb + ar * HAST + kk + 2 * lc + 8);
                unsigned a3 = ldh2(Asb + (ar + 8) * HAST + kk + 2 * lc + 8);
#pragma unroll
                for (int nt = 0; nt < 4; nt++)
                    mma_f16(c[mt][nt], a0, a1, a2, a3, bf[nt][0], bf[nt][1]);
            }
        }
        if (++st == 3) st = 0;
    }

#pragma unroll
    for (int mt = 0; mt < 4; mt++) {
        int r0 = m0 + wm * 64 + mt * 16 + lr;
        int r1 = r0 + 8;
#pragma unroll
        for (int nt = 0; nt < 4; nt++) {
            int n = n0 + wn * 32 + nt * 8 + lc * 2;
            float b0v = bias[n], b1v = bias[n + 1];
            store_pair(csel, Cext, r0, n, c[mt][nt][0] + b0v, c[mt][nt][1] + b1v);
            store_pair(csel, Cext, r1, n, c[mt][nt][2] + b0v, c[mt][nt][3] + b1v);
        }
    }
}

// ---------------------------------------------------------------------------
// FP16 flash attention: 128 q-rows/CTA, 8 warps, warp tile 16x64, m16n8k16.
// In-warp softmax; PV A-frags are direct half2 packs of the S C-frags
// (natural layout match — zero shuffles). V transposed [d][s] in smem.
// ---------------------------------------------------------------------------
#define QST2 72
#define KST2 72
#define VST2 72
#define NT  ((SEQ + 63) / 64)   // 22

__global__ __launch_bounds__(256, 2) void attn_f16()
{
    extern __shared__ __half sma[];
    __half* Qs = sma;                      // [128][72]
    __half* Ks = Qs + 128 * QST2;          // [2][64][72]
    __half* Vs = Ks + 2 * 64 * KST2;       // [2][64][72]  (rows = d, cols = s)

    int tid = threadIdx.x;
    int w = tid >> 5, lane = tid & 31;
    int lr = lane >> 2, lc = lane & 3;

    int bh = blockIdx.y;
    int b = bh >> 4;
    int h = bh & 15;
    int q0 = blockIdx.x * 128;

    const __half* Qg  = g_qh + ((size_t)(b * HEADS + h)) * SEQ * HDIM;
    const __half* Kg  = g_kh + ((size_t)(b * HEADS + h)) * SEQ * HDIM;
    const __half* VgT = g_vT + ((size_t)(b * HEADS + h)) * HDIM * SEQP;

    // Q tile via cp.async (folded into first commit group)
#pragma unroll
    for (int i = 0; i < 4; i++) {
        int idx = tid + i * 256;           // 0..1023
        int r = idx >> 3;
        int c8 = (idx & 7) * 8;
        cp16(Qs + r * QST2 + c8, Qg + (size_t)(q0 + r) * HDIM + c8, (q0 + r) < SEQ);
    }

#define A_ISSUE(T, S)                                                          \
    do {                                                                       \
        int _k0 = (T) * 64;                                                    \
        __half* _Kd = Ks + (S) * 64 * KST2;                                    \
        __half* _Vd = Vs + (S) * 64 * VST2;                                    \
        _Pragma("unroll")                                                      \
        for (int _i = 0; _i < 2; _i++) {                                       \
            int _idx = tid + _i * 256;     /* 0..511 */                        \
            int _r = _idx >> 3;                                                \
            int _c8 = (_idx & 7) * 8;                                          \
            cp16(_Kd + _r * KST2 + _c8,                                        \
                 Kg + (size_t)(_k0 + _r) * HDIM + _c8, (_k0 + _r) < SEQ);      \
            cp16(_Vd + _r * VST2 + _c8,                                        \
                 VgT + (size_t)_r * SEQP + _k0 + _c8, (_k0 + _c8) < SEQ);      \
        }                                                                      \
        CP_COMMIT();                                                           \
    } while (0)

    float o[8][4];
#pragma unroll
    for (int od = 0; od < 8; od++)
#pragma unroll
        for (int i = 0; i < 4; i++) o[od][i] = 0.f;
    float m0v = -INFINITY, m1v = -INFINITY, l0 = 0.f, l1 = 0.f;

    int qr = w * 16 + lr;

    A_ISSUE(0, 0);

    for (int t = 0; t < NT; t++) {
        CP_WAIT0();
        __syncthreads();
        if (t + 1 < NT) A_ISSUE(t + 1, (t + 1) & 1);

        const __half* Ksb = Ks + (t & 1) * 64 * KST2;
        const __half* Vsb = Vs + (t & 1) * 64 * VST2;

        // S(16x64) = Q @ K^T  (4 k16-blocks x 8 n-octets = 32 MMAs)
        float s[8][4];
#pragma unroll
        for (int nt = 0; nt < 8; nt++)
#pragma unroll
            for (int i = 0; i < 4; i++) s[nt][i] = 0.f;

#pragma unroll
        for (int kb = 0; kb < 4; kb++) {
            int kk = kb * 16;
            unsigned a0 = ldh2(Qs + qr * QST2 + kk + 2 * lc);
            unsigned a1 = ldh2(Qs + (qr + 8) * QST2 + kk + 2 * lc);
            unsigned a2 = ldh2(Qs + qr * QST2 + kk + 2 * lc + 8);
            unsigned a3 = ldh2(Qs + (qr + 8) * QST2 + kk + 2 * lc + 8);
#pragma unroll
            for (int nt = 0; nt < 8; nt++) {
                int krow = nt * 8 + lr;
                unsigned b0 = ldh2(Ksb + krow * KST2 + kk + 2 * lc);
                unsigned b1 = ldh2(Ksb + krow * KST2 + kk + 2 * lc + 8);
                mma_f16(s[nt], a0, a1, a2, a3, b0, b1);
            }
        }

        // Mask only on the final partial tile
        if (t == NT - 1) {
#pragma unroll
            for (int nt = 0; nt < 8; nt++)
#pragma unroll
                for (int e = 0; e < 2; e++) {
                    int col = t * 64 + nt * 8 + 2 * lc + e;
                    if (col >= SEQ) { s[nt][e] = -INFINITY; s[nt][2 + e] = -INFINITY; }
                }
        }

        // In-warp row max
        float rmax0 = -INFINITY, rmax1 = -INFINITY;
#pragma unroll
        for (int nt = 0; nt < 8; nt++) {
            rmax0 = fmaxf(rmax0, fmaxf(s[nt][0], s[nt][1]));
            rmax1 = fmaxf(rmax1, fmaxf(s[nt][2], s[nt][3]));
        }
        rmax0 = fmaxf(rmax0, __shfl_xor_sync(0xffffffffu, rmax0, 1));
        rmax0 = fmaxf(rmax0, __shfl_xor_sync(0xffffffffu, rmax0, 2));
        rmax1 = fmaxf(rmax1, __shfl_xor_sync(0xffffffffu, rmax1, 1));
        rmax1 = fmaxf(rmax1, __shfl_xor_sync(0xffffffffu, rmax1, 2));

        float mn0 = fmaxf(m0v, rmax0);
        float mn1 = fmaxf(m1v, rmax1);
        float alpha0 = ex2(m0v - mn0);
        float alpha1 = ex2(m1v - mn1);
        m0v = mn0; m1v = mn1;

        float sum0 = 0.f, sum1 = 0.f;
#pragma unroll
        for (int nt = 0; nt < 8; nt++) {
#pragma unroll
            for (int e = 0; e < 2; e++) {
                float p0 = ex2(s[nt][e] - mn0);
                float p1 = ex2(s[nt][2 + e] - mn1);
                sum0 += p0; sum1 += p1;
                s[nt][e] = p0;
                s[nt][2 + e] = p1;
            }
        }
        sum0 += __shfl_xor_sync(0xffffffffu, sum0, 1);
        sum0 += __shfl_xor_sync(0xffffffffu, sum0, 2);
        sum1 += __shfl_xor_sync(0xffffffffu, sum1, 1);
        sum1 += __shfl_xor_sync(0xffffffffu, sum1, 2);
        l0 = l0 * alpha0 + sum0;
        l1 = l1 * alpha1 + sum1;

#pragma unroll
        for (int od = 0; od < 8; od++) {
            o[od][0] *= alpha0; o[od][1] *= alpha0;
            o[od][2] *= alpha1; o[od][3] *= alpha1;
        }

        // PV: A-frags = direct half2 packs of S C-frags (natural k16 layout).
        // B-frags from transposed V: b0={V[kk+2lc][col],V[kk+2lc+1][col]}.
#pragma unroll
        for (int kb = 0; kb < 4; kb++) {
            unsigned a0 = pack_h2(s[2 * kb][0],     s[2 * kb][1]);
            unsigned a1 = pack_h2(s[2 * kb][2],     s[2 * kb][3]);
            unsigned a2 = pack_h2(s[2 * kb + 1][0], s[2 * kb + 1][1]);
            unsigned a3 = pack_h2(s[2 * kb + 1][2], s[2 * kb + 1][3]);
            int kk = kb * 16;
#pragma unroll
            for (int od = 0; od < 8; od++) {
                int col = od * 8 + lr;
                unsigned b0 = ldh2(Vsb + col * VST2 + kk + 2 * lc);
                unsigned b1 = ldh2(Vsb + col * VST2 + kk + 2 * lc + 8);
                mma_f16(o[od], a0, a1, a2, a3, b0, b1);
            }
        }
    }

    // Epilogue: normalize, write fp16 ctx [B,S,D]
    float inv0 = 1.f / l0;
    float inv1 = 1.f / l1;
    int r0 = q0 + qr, r1 = r0 + 8;
#pragma unroll
    for (int od = 0; od < 8; od++) {
        int col = h * HDIM + od * 8 + lc * 2;
        if (r0 < SEQ)
            *(__half2*)&g_ch[((size_t)(b * SEQ + r0)) * DIM + col] =
                __floats2half2_rn(o[od][0] * inv0, o[od][1] * inv0);
        if (r1 < SEQ)
            *(__half2*)&g_ch[((size_t)(b * SEQ + r1)) * DIM + col] =
                __floats2half2_rn(o[od][2] * inv1, o[od][3] * inv1);
    }
}

// ---------------------------------------------------------------------------
extern "C" void kernel_launch(void* const* d_in, const int* in_sizes, int n_in,
                              void* d_out, int out_size)
{
    const float* x  = (const float*)d_in[0];
    const float* Wq = (const float*)d_in[1];
    const float* bq = (const float*)d_in[2];
    const float* Wk = (const float*)d_in[3];
    const float* bk = (const float*)d_in[4];
    const float* Wv = (const float*)d_in[5];
    const float* bv = (const float*)d_in[6];
    const float* Wo = (const float*)d_in[7];
    const float* bo = (const float*)d_in[8];
    float* out = (float*)d_out;

    round_x<<<(MROWS * DIM / 4 + 255) / 256, 256>>>(x);
    dim3 wtGrid(DIM / 32, DIM / 32, 4);
    round_wT<<<wtGrid, 256>>>(Wq, Wk, Wv, Wo);
    zero_vpad<<<(BATCH * HEADS * HDIM * (SEQP - SEQ) + 255) / 256, 256>>>();

    int gsm = 6 * HASTG * sizeof(__half);   // 61440
    cudaFuncSetAttribute(gemm_f16, cudaFuncAttributeMaxDynamicSharedMemorySize, gsm);

    dim3 qkvGrid((MROWS + 127) / 128, DIM / 128, 3);  // 86 x 8 x 3
    gemm_f16<<<qkvGrid, 256, gsm>>>(bq, bk, bv, nullptr, 0);

    int asm_ = (128 * QST2 + 2 * 64 * KST2 + 2 * 64 * VST2) * sizeof(__half);  // 55296
    cudaFuncSetAttribute(attn_f16, cudaFuncAttributeMaxDynamicSharedMemorySize, asm_);
    dim3 attnGrid((SEQ + 127) / 128, BATCH * HEADS);  // 11 x 128
    attn_f16<<<attnGrid, 256, asm_>>>();

    dim3 oGrid((MROWS + 127) / 128, DIM / 128, 1);
    gemm_f16<<<oGrid, 256, gsm>>>(bo, nullptr, nullptr, out, 1);
}

// round 15
// speedup vs baseline: 2.6007x; 1.0821x over previous
#include <cuda_runtime.h>
#include <cuda_fp16.h>
#include <math.h>
#include <stdint.h>

#define BATCH 8
#define SEQ 1370
#define SEQP 1376             // padded seq for 16B-aligned transposed-V rows
#define DIM 1024
#define HEADS 16
#define HDIM 64
#define MROWS (BATCH * SEQ)   // 10960

// Q pre-scale: 1/sqrt(64) * log2(e)  (softmax computed in base-2 domain)
#define QSCALE 0.18033688011112042f

// Scratch (allocation-free: device globals) — all fp16 operands
__device__ __align__(256) __half g_qh[BATCH * HEADS * SEQ * HDIM];   // [B,H,S,Dh] pre-scaled
__device__ __align__(256) __half g_kh[BATCH * HEADS * SEQ * HDIM];   // [B,H,S,Dh]
__device__ __align__(256) __half g_vT[BATCH * HEADS * HDIM * SEQP];  // [B,H,Dh,Sp] transposed
__device__ __align__(256) __half g_ch[BATCH * SEQ * DIM];            // [B,S,D]
__device__ __align__(256) __half g_xh[MROWS * DIM];                  // x rounded
__device__ __align__(256) __half g_wh[4 * DIM * DIM];                // W^T: [z][n][k]

__device__ __forceinline__ float ex2(float x) {
    float r; asm("ex2.approx.f32 %0, %1;" : "=f"(r) : "f"(x)); return r;
}
__device__ __forceinline__ unsigned pack_h2(float lo, float hi) {
    __half2 h = __floats2half2_rn(lo, hi);
    return *(unsigned*)&h;
}
__device__ __forceinline__ unsigned ldh2(const __half* p) {
    return *(const unsigned*)p;
}

__device__ __forceinline__ void mma_f16(float c[4],
    unsigned a0, unsigned a1, unsigned a2, unsigned a3,
    unsigned b0, unsigned b1)
{
    asm volatile(
        "mma.sync.aligned.m16n8k16.row.col.f32.f16.f16.f32 "
        "{%0,%1,%2,%3}, {%4,%5,%6,%7}, {%8,%9}, {%0,%1,%2,%3};"
        : "+f"(c[0]), "+f"(c[1]), "+f"(c[2]), "+f"(c[3])
        : "r"(a0), "r"(a1), "r"(a2), "r"(a3), "r"(b0), "r"(b1));
}

// ---- cp.async helpers ----
__device__ __forceinline__ void cp16(void* smem_dst, const void* gsrc, bool pred) {
    unsigned d = (unsigned)__cvta_generic_to_shared(smem_dst);
    int sz = pred ? 16 : 0;
    asm volatile("cp.async.cg.shared.global [%0], [%1], 16, %2;\n"
                 :: "r"(d), "l"(gsrc), "r"(sz));
}
#define CP_COMMIT() asm volatile("cp.async.commit_group;\n")
#define CP_WAIT0()  asm volatile("cp.async.wait_group 0;\n" ::: "memory")
#define CP_WAIT1()  asm volatile("cp.async.wait_group 1;\n" ::: "memory")

// ---------------------------------------------------------------------------
// Pre-rounding passes
// ---------------------------------------------------------------------------
__global__ __launch_bounds__(256) void round_x(const float* __restrict__ x)
{
    int i = blockIdx.x * blockDim.x + threadIdx.x;
    if (i >= MROWS * DIM / 4) return;
    float4 v = ((const float4*)x)[i];
    ((__half2*)g_xh)[2 * i]     = __floats2half2_rn(v.x, v.y);
    ((__half2*)g_xh)[2 * i + 1] = __floats2half2_rn(v.z, v.w);
}

// Transpose + round: g_wh[z][n][k] = half(W_z[k][n])
__global__ __launch_bounds__(256) void round_wT(
    const float* __restrict__ wq, const float* __restrict__ wk,
    const float* __restrict__ wv, const float* __restrict__ wo)
{
    __shared__ float t[32][33];
    int z = blockIdx.z;
    const float* W = (z == 0) ? wq : (z == 1) ? wk : (z == 2) ? wv : wo;
    int k0 = blockIdx.x * 32, n0 = blockIdx.y * 32;
    int tx = threadIdx.x & 31, ty = threadIdx.x >> 5;   // 32 x 8
#pragma unroll
    for (int i = 0; i < 4; i++)
        t[ty + 8 * i][tx] = W[(size_t)(k0 + ty + 8 * i) * DIM + n0 + tx];
    __syncthreads();
    __half* dst = g_wh + (size_t)z * DIM * DIM;
#pragma unroll
    for (int i = 0; i < 4; i++)
        dst[(size_t)(n0 + ty + 8 * i) * DIM + k0 + tx] = __float2half_rn(t[tx][ty + 8 * i]);
}

// Zero the transposed-V pad columns [SEQ, SEQP)
__global__ __launch_bounds__(256) void zero_vpad()
{
    int i = blockIdx.x * blockDim.x + threadIdx.x;
    int total = BATCH * HEADS * HDIM * (SEQP - SEQ);
    if (i >= total) return;
    int row = i / (SEQP - SEQ);
    int off = i % (SEQP - SEQ);
    g_vT[(size_t)row * SEQP + SEQ + off] = __float2half_rn(0.f);
}

// ---------------------------------------------------------------------------
// FP16 GEMM, 3-stage cp.async, BK=64/stage, m16n8k16. C = A@W + bias.
// 128x128 tile, 8 warps (2x4), warp tile 64x32. 16 mainloop iters, 16 barriers.
// mode 0: fused QKV (z selects); mode 1: out proj.
// ---------------------------------------------------------------------------
#define HAST 72                 // smem row stride in halves (BK64 + 8)
#define HASTG (128 * HAST)      // 9216 halves / stage

__device__ __forceinline__ void store_pair(int csel, float* __restrict__ Cext,
                                           int m, int n, float v0, float v1)
{
    if (m >= MROWS) return;
    int b = m / SEQ;
    int s = m - b * SEQ;
    if (csel == 0) {
        int h = n >> 6, d = n & 63;
        *(__half2*)&g_qh[(((size_t)(b * HEADS + h)) * SEQ + s) * HDIM + d] =
            __floats2half2_rn(v0 * QSCALE, v1 * QSCALE);
    } else if (csel == 1) {
        int h = n >> 6, d = n & 63;
        *(__half2*)&g_kh[(((size_t)(b * HEADS + h)) * SEQ + s) * HDIM + d] =
            __floats2half2_rn(v0, v1);
    } else if (csel == 2) {
        int h = n >> 6, d = n & 63;
        size_t base = ((size_t)(b * HEADS + h)) * HDIM;
        g_vT[(base + d) * SEQP + s]     = __float2half_rn(v0);
        g_vT[(base + d + 1) * SEQP + s] = __float2half_rn(v1);
    } else {
        *(float2*)&Cext[(size_t)m * DIM + n] = make_float2(v0, v1);
    }
}

__global__ __launch_bounds__(256, 2) void gemm_f16(
    const float* __restrict__ B0, const float* __restrict__ B1,
    const float* __restrict__ B2, float* __restrict__ Cext, int mode)
{
    extern __shared__ __half smh[];
    __half* As = smh;                 // [3][128*72]
    __half* Bs = smh + 3 * HASTG;     // [3][128*72]

    int z = (mode == 1) ? 3 : blockIdx.z;
    const __half* A    = (mode == 1) ? g_ch : g_xh;
    const __half* W    = g_wh + (size_t)z * DIM * DIM;   // [n][k]
    const float* bias  = (mode == 1) ? B0 : (z == 0 ? B0 : (z == 1 ? B1 : B2));
    int csel           = (mode == 1) ? 3 : z;

    int tid = threadIdx.x;
    int wid = tid >> 5, lane = tid & 31;
    int wm = wid & 1, wn = wid >> 1;
    int lr = lane >> 2, lc = lane & 3;
    int m0 = blockIdx.x * 128, n0 = blockIdx.y * 128;

    float c[4][4][4];
#pragma unroll
    for (int mt = 0; mt < 4; mt++)
#pragma unroll
        for (int nt = 0; nt < 4; nt++)
#pragma unroll
            for (int i = 0; i < 4; i++) c[mt][nt][i] = 0.f;

    // Loaders: 4 cp16/thread per operand per 128x64 stage
    int lrow[4], lc8[4];
    bool aval[4];
#pragma unroll
    for (int i = 0; i < 4; i++) {
        int idx = tid + i * 256;
        lrow[i] = idx >> 3;          // 0..127
        lc8[i] = (idx & 7) * 8;      // halves offset 0..56
        aval[i] = (m0 + lrow[i]) < MROWS;
    }

#define G_ISSUE(T, S)                                                            \
    do {                                                                         \
        int _k0 = (T) * 64;                                                      \
        __half* _Asd = As + (S) * HASTG;                                         \
        __half* _Bsd = Bs + (S) * HASTG;                                         \
        _Pragma("unroll")                                                        \
        for (int _i = 0; _i < 4; _i++) {                                         \
            cp16(_Asd + lrow[_i] * HAST + lc8[_i],                               \
                 A + (size_t)(m0 + lrow[_i]) * DIM + _k0 + lc8[_i], aval[_i]);   \
            cp16(_Bsd + lrow[_i] * HAST + lc8[_i],                               \
                 W + (size_t)(n0 + lrow[_i]) * DIM + _k0 + lc8[_i], true);       \
        }                                                                        \
        CP_COMMIT();                                                             \
    } while (0)

    G_ISSUE(0, 0);
    G_ISSUE(1, 1);

    int st = 0;
    for (int t = 0; t < 16; t++) {
        if (t + 1 < 16) CP_WAIT1(); else CP_WAIT0();
        __syncthreads();
        if (t + 2 < 16) {
            int s2 = st + 2; if (s2 >= 3) s2 -= 3;
            G_ISSUE(t + 2, s2);
        }

        const __half* Asb = As + st * HASTG;
        const __half* Bsb = Bs + st * HASTG;

#pragma unroll
        for (int ks = 0; ks < 4; ks++) {
            int kk = ks * 16;
            unsigned bf[4][2];
#pragma unroll
            for (int nt = 0; nt < 4; nt++) {
                int col = wn * 32 + nt * 8 + lr;
                bf[nt][0] = ldh2(Bsb + col * HAST + kk + 2 * lc);
                bf[nt][1] = ldh2(Bsb + col * HAST + kk + 2 * lc + 8);
            }
#pragma unroll
            for (int mt = 0; mt < 4; mt++) {
                int ar = wm * 64 + mt * 16 + lr;
                unsigned a0 = ldh2(Asb + ar * HAST + kk + 2 * lc);
                unsigned a1 = ldh2(Asb + (ar + 8) * HAST + kk + 2 * lc);
                unsigned a2 = ldh2(Asb + ar * HAST + kk + 2 * lc + 8);
                unsigned a3 = ldh2(Asb + (ar + 8) * HAST + kk + 2 * lc + 8);
#pragma unroll
                for (int nt = 0; nt < 4; nt++)
                    mma_f16(c[mt][nt], a0, a1, a2, a3, bf[nt][0], bf[nt][1]);
            }
        }
        if (++st == 3) st = 0;
    }

#pragma unroll
    for (int mt = 0; mt < 4; mt++) {
        int r0 = m0 + wm * 64 + mt * 16 + lr;
        int r1 = r0 + 8;
#pragma unroll
        for (int nt = 0; nt < 4; nt++) {
            int n = n0 + wn * 32 + nt * 8 + lc * 2;
            float b0v = bias[n], b1v = bias[n + 1];
            store_pair(csel, Cext, r0, n, c[mt][nt][0] + b0v, c[mt][nt][1] + b1v);
            store_pair(csel, Cext, r1, n, c[mt][nt][2] + b0v, c[mt][nt][3] + b1v);
        }
    }
}

// ---------------------------------------------------------------------------
// FP16 flash attention: 128 q-rows/CTA, 8 warps, warp tile 16x64, m16n8k16,
// 3-stage cp.async K/V ring. In-warp softmax; PV A-frags are direct half2
// packs of S C-frags (zero shuffles). V transposed [d][s] in smem.
// ---------------------------------------------------------------------------
#define QST2 72
#define KST2 72
#define VST2 72
#define KVSTG (64 * KST2)        // halves per K (or V) stage
#define NT  ((SEQ + 63) / 64)    // 22

__global__ __launch_bounds__(256, 2) void attn_f16()
{
    extern __shared__ __half sma[];
    __half* Qs = sma;                      // [128][72]
    __half* Ks = Qs + 128 * QST2;          // [3][64][72]
    __half* Vs = Ks + 3 * KVSTG;           // [3][64][72]  (rows = d, cols = s)

    int tid = threadIdx.x;
    int w = tid >> 5, lane = tid & 31;
    int lr = lane >> 2, lc = lane & 3;

    int bh = blockIdx.y;
    int b = bh >> 4;
    int h = bh & 15;
    int q0 = blockIdx.x * 128;

    const __half* Qg  = g_qh + ((size_t)(b * HEADS + h)) * SEQ * HDIM;
    const __half* Kg  = g_kh + ((size_t)(b * HEADS + h)) * SEQ * HDIM;
    const __half* VgT = g_vT + ((size_t)(b * HEADS + h)) * HDIM * SEQP;

    // Q tile via cp.async (folded into first commit group)
#pragma unroll
    for (int i = 0; i < 4; i++) {
        int idx = tid + i * 256;           // 0..1023
        int r = idx >> 3;
        int c8 = (idx & 7) * 8;
        cp16(Qs + r * QST2 + c8, Qg + (size_t)(q0 + r) * HDIM + c8, (q0 + r) < SEQ);
    }

#define A_ISSUE(T, S)                                                          \
    do {                                                                       \
        int _k0 = (T) * 64;                                                    \
        __half* _Kd = Ks + (S) * KVSTG;                                        \
        __half* _Vd = Vs + (S) * KVSTG;                                        \
        _Pragma("unroll")                                                      \
        for (int _i = 0; _i < 2; _i++) {                                       \
            int _idx = tid + _i * 256;     /* 0..511 */                        \
            int _r = _idx >> 3;                                                \
            int _c8 = (_idx & 7) * 8;                                          \
            cp16(_Kd + _r * KST2 + _c8,                                        \
                 Kg + (size_t)(_k0 + _r) * HDIM + _c8, (_k0 + _r) < SEQ);      \
            cp16(_Vd + _r * VST2 + _c8,                                        \
                 VgT + (size_t)_r * SEQP + _k0 + _c8, (_k0 + _c8) < SEQ);      \
        }                                                                      \
        CP_COMMIT();                                                           \
    } while (0)

    float o[8][4];
#pragma unroll
    for (int od = 0; od < 8; od++)
#pragma unroll
        for (int i = 0; i < 4; i++) o[od][i] = 0.f;
    float m0v = -INFINITY, m1v = -INFINITY, l0 = 0.f, l1 = 0.f;

    int qr = w * 16 + lr;

    A_ISSUE(0, 0);   // includes Q copies
    A_ISSUE(1, 1);

    int st = 0;
    for (int t = 0; t < NT; t++) {
        if (t + 1 < NT) CP_WAIT1(); else CP_WAIT0();
        __syncthreads();
        if (t + 2 < NT) {
            int s2 = st + 2; if (s2 >= 3) s2 -= 3;
            A_ISSUE(t + 2, s2);
        }

        const __half* Ksb = Ks + st * KVSTG;
        const __half* Vsb = Vs + st * KVSTG;

        // S(16x64) = Q @ K^T  (4 k16-blocks x 8 n-octets = 32 MMAs)
        float s[8][4];
#pragma unroll
        for (int nt = 0; nt < 8; nt++)
#pragma unroll
            for (int i = 0; i < 4; i++) s[nt][i] = 0.f;

#pragma unroll
        for (int kb = 0; kb < 4; kb++) {
            int kk = kb * 16;
            unsigned a0 = ldh2(Qs + qr * QST2 + kk + 2 * lc);
            unsigned a1 = ldh2(Qs + (qr + 8) * QST2 + kk + 2 * lc);
            unsigned a2 = ldh2(Qs + qr * QST2 + kk + 2 * lc + 8);
            unsigned a3 = ldh2(Qs + (qr + 8) * QST2 + kk + 2 * lc + 8);
#pragma unroll
            for (int nt = 0; nt < 8; nt++) {
                int krow = nt * 8 + lr;
                unsigned b0 = ldh2(Ksb + krow * KST2 + kk + 2 * lc);
                unsigned b1 = ldh2(Ksb + krow * KST2 + kk + 2 * lc + 8);
                mma_f16(s[nt], a0, a1, a2, a3, b0, b1);
            }
        }

        // Mask only on the final partial tile
        if (t == NT - 1) {
#pragma unroll
            for (int nt = 0; nt < 8; nt++)
#pragma unroll
                for (int e = 0; e < 2; e++) {
                    int col = t * 64 + nt * 8 + 2 * lc + e;
                    if (col >= SEQ) { s[nt][e] = -INFINITY; s[nt][2 + e] = -INFINITY; }
                }
        }

        // In-warp row max
        float rmax0 = -INFINITY, rmax1 = -INFINITY;
#pragma unroll
        for (int nt = 0; nt < 8; nt++) {
            rmax0 = fmaxf(rmax0, fmaxf(s[nt][0], s[nt][1]));
            rmax1 = fmaxf(rmax1, fmaxf(s[nt][2], s[nt][3]));
        }
        rmax0 = fmaxf(rmax0, __shfl_xor_sync(0xffffffffu, rmax0, 1));
        rmax0 = fmaxf(rmax0, __shfl_xor_sync(0xffffffffu, rmax0, 2));
        rmax1 = fmaxf(rmax1, __shfl_xor_sync(0xffffffffu, rmax1, 1));
        rmax1 = fmaxf(rmax1, __shfl_xor_sync(0xffffffffu, rmax1, 2));

        float mn0 = fmaxf(m0v, rmax0);
        float mn1 = fmaxf(m1v, rmax1);
        float alpha0 = ex2(m0v - mn0);
        float alpha1 = ex2(m1v - mn1);
        m0v = mn0; m1v = mn1;

        float sum0 = 0.f, sum1 = 0.f;
#pragma unroll
        for (int nt = 0; nt < 8; nt++) {
#pragma unroll
            for (int e = 0; e < 2; e++) {
                float p0 = ex2(s[nt][e] - mn0);
                float p1 = ex2(s[nt][2 + e] - mn1);
                sum0 += p0; sum1 += p1;
                s[nt][e] = p0;
                s[nt][2 + e] = p1;
            }
        }
        sum0 += __shfl_xor_sync(0xffffffffu, sum0, 1);
        sum0 += __shfl_xor_sync(0xffffffffu, sum0, 2);
        sum1 += __shfl_xor_sync(0xffffffffu, sum1, 1);
        sum1 += __shfl_xor_sync(0xffffffffu, sum1, 2);
        l0 = l0 * alpha0 + sum0;
        l1 = l1 * alpha1 + sum1;

#pragma unroll
        for (int od = 0; od < 8; od++) {
            o[od][0] *= alpha0; o[od][1] *= alpha0;
            o[od][2] *= alpha1; o[od][3] *= alpha1;
        }

        // PV: A-frags = direct half2 packs of S C-frags (natural k16 layout).
#pragma unroll
        for (int kb = 0; kb < 4; kb++) {
            unsigned a0 = pack_h2(s[2 * kb][0],     s[2 * kb][1]);
            unsigned a1 = pack_h2(s[2 * kb][2],     s[2 * kb][3]);
            unsigned a2 = pack_h2(s[2 * kb + 1][0], s[2 * kb + 1][1]);
            unsigned a3 = pack_h2(s[2 * kb + 1][2], s[2 * kb + 1][3]);
            int kk = kb * 16;
#pragma unroll
            for (int od = 0; od < 8; od++) {
                int col = od * 8 + lr;
                unsigned b0 = ldh2(Vsb + col * VST2 + kk + 2 * lc);
                unsigned b1 = ldh2(Vsb + col * VST2 + kk + 2 * lc + 8);
                mma_f16(o[od], a0, a1, a2, a3, b0, b1);
            }
        }
        if (++st == 3) st = 0;
    }

    // Epilogue: normalize, write fp16 ctx [B,S,D]
    float inv0 = 1.f / l0;
    float inv1 = 1.f / l1;
    int r0 = q0 + qr, r1 = r0 + 8;
#pragma unroll
    for (int od = 0; od < 8; od++) {
        int col = h * HDIM + od * 8 + lc * 2;
        if (r0 < SEQ)
            *(__half2*)&g_ch[((size_t)(b * SEQ + r0)) * DIM + col] =
                __floats2half2_rn(o[od][0] * inv0, o[od][1] * inv0);
        if (r1 < SEQ)
            *(__half2*)&g_ch[((size_t)(b * SEQ + r1)) * DIM + col] =
                __floats2half2_rn(o[od][2] * inv1, o[od][3] * inv1);
    }
}

// ---------------------------------------------------------------------------
extern "C" void kernel_launch(void* const* d_in, const int* in_sizes, int n_in,
                              void* d_out, int out_size)
{
    const float* x  = (const float*)d_in[0];
    const float* Wq = (const float*)d_in[1];
    const float* bq = (const float*)d_in[2];
    const float* Wk = (const float*)d_in[3];
    const float* bk = (const float*)d_in[4];
    const float* Wv = (const float*)d_in[5];
    const float* bv = (const float*)d_in[6];
    const float* Wo = (const float*)d_in[7];
    const float* bo = (const float*)d_in[8];
    float* out = (float*)d_out;

    round_x<<<(MROWS * DIM / 4 + 255) / 256, 256>>>(x);
    dim3 wtGrid(DIM / 32, DIM / 32, 4);
    round_wT<<<wtGrid, 256>>>(Wq, Wk, Wv, Wo);
    zero_vpad<<<(BATCH * HEADS * HDIM * (SEQP - SEQ) + 255) / 256, 256>>>();

    int gsm = 6 * HASTG * sizeof(__half);   // 110592
    cudaFuncSetAttribute(gemm_f16, cudaFuncAttributeMaxDynamicSharedMemorySize, gsm);

    dim3 qkvGrid((MROWS + 127) / 128, DIM / 128, 3);  // 86 x 8 x 3
    gemm_f16<<<qkvGrid, 256, gsm>>>(bq, bk, bv, nullptr, 0);

    int asm_ = (128 * QST2 + 6 * KVSTG) * sizeof(__half);  // 73728
    cudaFuncSetAttribute(attn_f16, cudaFuncAttributeMaxDynamicSharedMemorySize, asm_);
    dim3 attnGrid((SEQ + 127) / 128, BATCH * HEADS);  // 11 x 128
    attn_f16<<<attnGrid, 256, asm_>>>();

    dim3 oGrid((MROWS + 127) / 128, DIM / 128, 1);
    gemm_f16<<<oGrid, 256, gsm>>>(bo, nullptr, nullptr, out, 1);
}

// round 16
// speedup vs baseline: 2.8340x; 1.0897x over previous
#include <cuda_runtime.h>
#include <cuda_fp16.h>
#include <math.h>
#include <stdint.h>

#define BATCH 8
#define SEQ 1370
#define SEQP 1376             // padded seq for 16B-aligned transposed-V rows
#define DIM 1024
#define HEADS 16
#define HDIM 64
#define MROWS (BATCH * SEQ)   // 10960

// Q pre-scale: 1/sqrt(64) * log2(e)  (softmax computed in base-2 domain)
#define QSCALE 0.18033688011112042f

// Scratch (allocation-free: device globals) — all fp16 operands
__device__ __align__(256) __half g_qh[BATCH * HEADS * SEQ * HDIM];   // [B,H,S,Dh] pre-scaled
__device__ __align__(256) __half g_kh[BATCH * HEADS * SEQ * HDIM];   // [B,H,S,Dh]
__device__ __align__(256) __half g_vT[BATCH * HEADS * HDIM * SEQP];  // [B,H,Dh,Sp] transposed
__device__ __align__(256) __half g_ch[BATCH * SEQ * DIM];            // [B,S,D]
__device__ __align__(256) __half g_xh[MROWS * DIM];                  // x rounded
__device__ __align__(256) __half g_wh[4 * DIM * DIM];                // W^T: [z][n][k]

__device__ __forceinline__ float ex2(float x) {
    float r; asm("ex2.approx.f32 %0, %1;" : "=f"(r) : "f"(x)); return r;
}
__device__ __forceinline__ unsigned pack_h2(float lo, float hi) {
    __half2 h = __floats2half2_rn(lo, hi);
    return *(unsigned*)&h;
}

__device__ __forceinline__ void mma_f16(float c[4],
    unsigned a0, unsigned a1, unsigned a2, unsigned a3,
    unsigned b0, unsigned b1)
{
    asm volatile(
        "mma.sync.aligned.m16n8k16.row.col.f32.f16.f16.f32 "
        "{%0,%1,%2,%3}, {%4,%5,%6,%7}, {%8,%9}, {%0,%1,%2,%3};"
        : "+f"(c[0]), "+f"(c[1]), "+f"(c[2]), "+f"(c[3])
        : "r"(a0), "r"(a1), "r"(a2), "r"(a3), "r"(b0), "r"(b1));
}

// ldmatrix x4: four 8x8 b16 tiles, lane l supplies row address
__device__ __forceinline__ void ldsm4(unsigned r[4], const __half* p) {
    unsigned a = (unsigned)__cvta_generic_to_shared(p);
    asm volatile("ldmatrix.sync.aligned.m8n8.x4.shared.b16 {%0,%1,%2,%3}, [%4];"
                 : "=r"(r[0]), "=r"(r[1]), "=r"(r[2]), "=r"(r[3]) : "r"(a));
}

// ---- cp.async helpers ----
__device__ __forceinline__ void cp16(void* smem_dst, const void* gsrc, bool pred) {
    unsigned d = (unsigned)__cvta_generic_to_shared(smem_dst);
    int sz = pred ? 16 : 0;
    asm volatile("cp.async.cg.shared.global [%0], [%1], 16, %2;\n"
                 :: "r"(d), "l"(gsrc), "r"(sz));
}
#define CP_COMMIT() asm volatile("cp.async.commit_group;\n")
#define CP_WAIT0()  asm volatile("cp.async.wait_group 0;\n" ::: "memory")
#define CP_WAIT1()  asm volatile("cp.async.wait_group 1;\n" ::: "memory")

// ---------------------------------------------------------------------------
// Pre-rounding passes
// ---------------------------------------------------------------------------
__global__ __launch_bounds__(256) void round_x(const float* __restrict__ x)
{
    int i = blockIdx.x * blockDim.x + threadIdx.x;
    if (i >= MROWS * DIM / 4) return;
    float4 v = ((const float4*)x)[i];
    ((__half2*)g_xh)[2 * i]     = __floats2half2_rn(v.x, v.y);
    ((__half2*)g_xh)[2 * i + 1] = __floats2half2_rn(v.z, v.w);
}

// Transpose + round: g_wh[z][n][k] = half(W_z[k][n])
__global__ __launch_bounds__(256) void round_wT(
    const float* __restrict__ wq, const float* __restrict__ wk,
    const float* __restrict__ wv, const float* __restrict__ wo)
{
    __shared__ float t[32][33];
    int z = blockIdx.z;
    const float* W = (z == 0) ? wq : (z == 1) ? wk : (z == 2) ? wv : wo;
    int k0 = blockIdx.x * 32, n0 = blockIdx.y * 32;
    int tx = threadIdx.x & 31, ty = threadIdx.x >> 5;   // 32 x 8
#pragma unroll
    for (int i = 0; i < 4; i++)
        t[ty + 8 * i][tx] = W[(size_t)(k0 + ty + 8 * i) * DIM + n0 + tx];
    __syncthreads();
    __half* dst = g_wh + (size_t)z * DIM * DIM;
#pragma unroll
    for (int i = 0; i < 4; i++)
        dst[(size_t)(n0 + ty + 8 * i) * DIM + k0 + tx] = __float2half_rn(t[tx][ty + 8 * i]);
}

// Zero the transposed-V pad columns [SEQ, SEQP)
__global__ __launch_bounds__(256) void zero_vpad()
{
    int i = blockIdx.x * blockDim.x + threadIdx.x;
    int total = BATCH * HEADS * HDIM * (SEQP - SEQ);
    if (i >= total) return;
    int row = i / (SEQP - SEQ);
    int off = i % (SEQP - SEQ);
    g_vT[(size_t)row * SEQP + SEQ + off] = __float2half_rn(0.f);
}

// ---------------------------------------------------------------------------
// FP16 GEMM, 3-stage cp.async, BK=64/stage, m16n8k16, ldmatrix operand fetch.
// 128x128 tile, 8 warps (2x4), warp tile 64x32.
// ---------------------------------------------------------------------------
#define HAST 72                 // smem row stride in halves (BK64 + 8)
#define HASTG (128 * HAST)      // 9216 halves / stage

__device__ __forceinline__ void store_pair(int csel, float* __restrict__ Cext,
                                           int m, int n, float v0, float v1)
{
    if (m >= MROWS) return;
    int b = m / SEQ;
    int s = m - b * SEQ;
    if (csel == 0) {
        int h = n >> 6, d = n & 63;
        *(__half2*)&g_qh[(((size_t)(b * HEADS + h)) * SEQ + s) * HDIM + d] =
            __floats2half2_rn(v0 * QSCALE, v1 * QSCALE);
    } else if (csel == 1) {
        int h = n >> 6, d = n & 63;
        *(__half2*)&g_kh[(((size_t)(b * HEADS + h)) * SEQ + s) * HDIM + d] =
            __floats2half2_rn(v0, v1);
    } else if (csel == 2) {
        int h = n >> 6, d = n & 63;
        size_t base = ((size_t)(b * HEADS + h)) * HDIM;
        g_vT[(base + d) * SEQP + s]     = __float2half_rn(v0);
        g_vT[(base + d + 1) * SEQP + s] = __float2half_rn(v1);
    } else {
        *(float2*)&Cext[(size_t)m * DIM + n] = make_float2(v0, v1);
    }
}

__global__ __launch_bounds__(256, 2) void gemm_f16(
    const float* __restrict__ B0, const float* __restrict__ B1,
    const float* __restrict__ B2, float* __restrict__ Cext, int mode)
{
    extern __shared__ __half smh[];
    __half* As = smh;                 // [3][128*72]
    __half* Bs = smh + 3 * HASTG;     // [3][128*72]

    int z = (mode == 1) ? 3 : blockIdx.z;
    const __half* A    = (mode == 1) ? g_ch : g_xh;
    const __half* W    = g_wh + (size_t)z * DIM * DIM;   // [n][k]
    const float* bias  = (mode == 1) ? B0 : (z == 0 ? B0 : (z == 1 ? B1 : B2));
    int csel           = (mode == 1) ? 3 : z;

    int tid = threadIdx.x;
    int wid = tid >> 5, lane = tid & 31;
    int wm = wid & 1, wn = wid >> 1;
    int lr = lane >> 2, lc = lane & 3;
    int m0 = blockIdx.x * 128, n0 = blockIdx.y * 128;

    // ldmatrix lane address components
    int lane15 = lane & 15;
    int ak8   = (lane >> 4) << 3;              // A: k offset 0/8
    int browl = ((lane >> 4) << 3) + (lane & 7);  // B: row 0-15 pattern
    int bk8   = ((lane >> 3) & 1) << 3;        // B: k offset 0/8

    float c[4][4][4];
#pragma unroll
    for (int mt = 0; mt < 4; mt++)
#pragma unroll
        for (int nt = 0; nt < 4; nt++)
#pragma unroll
            for (int i = 0; i < 4; i++) c[mt][nt][i] = 0.f;

    // Loaders: 4 cp16/thread per operand per 128x64 stage
    int lrow[4], lc8[4];
    bool aval[4];
#pragma unroll
    for (int i = 0; i < 4; i++) {
        int idx = tid + i * 256;
        lrow[i] = idx >> 3;          // 0..127
        lc8[i] = (idx & 7) * 8;      // halves offset 0..56
        aval[i] = (m0 + lrow[i]) < MROWS;
    }

#define G_ISSUE(T, S)                                                            \
    do {                                                                         \
        int _k0 = (T) * 64;                                                      \
        __half* _Asd = As + (S) * HASTG;                                         \
        __half* _Bsd = Bs + (S) * HASTG;                                         \
        _Pragma("unroll")                                                        \
        for (int _i = 0; _i < 4; _i++) {                                         \
            cp16(_Asd + lrow[_i] * HAST + lc8[_i],                               \
                 A + (size_t)(m0 + lrow[_i]) * DIM + _k0 + lc8[_i], aval[_i]);   \
            cp16(_Bsd + lrow[_i] * HAST + lc8[_i],                               \
                 W + (size_t)(n0 + lrow[_i]) * DIM + _k0 + lc8[_i], true);       \
        }                                                                        \
        CP_COMMIT();                                                             \
    } while (0)

    G_ISSUE(0, 0);
    G_ISSUE(1, 1);

    int st = 0;
    for (int t = 0; t < 16; t++) {
        if (t + 1 < 16) CP_WAIT1(); else CP_WAIT0();
        __syncthreads();
        if (t + 2 < 16) {
            int s2 = st + 2; if (s2 >= 3) s2 -= 3;
            G_ISSUE(t + 2, s2);
        }

        const __half* Asb = As + st * HASTG;
        const __half* Bsb = Bs + st * HASTG;

#pragma unroll
        for (int ks = 0; ks < 4; ks++) {
            int kk = ks * 16;
            // B fragments: 2 x ldmatrix.x4 covers all 4 n-octets
            unsigned bf[2][4];
            ldsm4(bf[0], Bsb + (wn * 32 + browl) * HAST + kk + bk8);
            ldsm4(bf[1], Bsb + (wn * 32 + 16 + browl) * HAST + kk + bk8);
            // A fragments: 1 x ldmatrix.x4 per mt
#pragma unroll
            for (int mt = 0; mt < 4; mt++) {
                unsigned af[4];
                ldsm4(af, Asb + (wm * 64 + mt * 16 + lane15) * HAST + kk + ak8);
#pragma unroll
                for (int nt = 0; nt < 4; nt++)
                    mma_f16(c[mt][nt], af[0], af[1], af[2], af[3],
                            bf[nt >> 1][(nt & 1) * 2], bf[nt >> 1][(nt & 1) * 2 + 1]);
            }
        }
        if (++st == 3) st = 0;
    }

#pragma unroll
    for (int mt = 0; mt < 4; mt++) {
        int r0 = m0 + wm * 64 + mt * 16 + lr;
        int r1 = r0 + 8;
#pragma unroll
        for (int nt = 0; nt < 4; nt++) {
            int n = n0 + wn * 32 + nt * 8 + lc * 2;
            float b0v = bias[n], b1v = bias[n + 1];
            store_pair(csel, Cext, r0, n, c[mt][nt][0] + b0v, c[mt][nt][1] + b1v);
            store_pair(csel, Cext, r1, n, c[mt][nt][2] + b0v, c[mt][nt][3] + b1v);
        }
    }
}

// ---------------------------------------------------------------------------
// FP16 flash attention: 128 q-rows/CTA, 8 warps, warp tile 16x64, m16n8k16,
// 3-stage cp.async K/V ring, ldmatrix operand fetch. In-warp softmax; PV
// A-frags are direct half2 packs of S C-frags. V transposed [d][s] in smem.
// ---------------------------------------------------------------------------
#define QST2 72
#define KST2 72
#define VST2 72
#define KVSTG (64 * KST2)        // halves per K (or V) stage
#define NT  ((SEQ + 63) / 64)    // 22

__global__ __launch_bounds__(256, 2) void attn_f16()
{
    extern __shared__ __half sma[];
    __half* Qs = sma;                      // [128][72]
    __half* Ks = Qs + 128 * QST2;          // [3][64][72]
    __half* Vs = Ks + 3 * KVSTG;           // [3][64][72]  (rows = d, cols = s)

    int tid = threadIdx.x;
    int w = tid >> 5, lane = tid & 31;
    int lr = lane >> 2, lc = lane & 3;

    int lane15 = lane & 15;
    int ak8   = (lane >> 4) << 3;
    int browl = ((lane >> 4) << 3) + (lane & 7);
    int bk8   = ((lane >> 3) & 1) << 3;

    int bh = blockIdx.y;
    int b = bh >> 4;
    int h = bh & 15;
    int q0 = blockIdx.x * 128;

    const __half* Qg  = g_qh + ((size_t)(b * HEADS + h)) * SEQ * HDIM;
    const __half* Kg  = g_kh + ((size_t)(b * HEADS + h)) * SEQ * HDIM;
    const __half* VgT = g_vT + ((size_t)(b * HEADS + h)) * HDIM * SEQP;

    // Q tile via cp.async (folded into first commit group)
#pragma unroll
    for (int i = 0; i < 4; i++) {
        int idx = tid + i * 256;           // 0..1023
        int r = idx >> 3;
        int c8 = (idx & 7) * 8;
        cp16(Qs + r * QST2 + c8, Qg + (size_t)(q0 + r) * HDIM + c8, (q0 + r) < SEQ);
    }

#define A_ISSUE(T, S)                                                          \
    do {                                                                       \
        int _k0 = (T) * 64;                                                    \
        __half* _Kd = Ks + (S) * KVSTG;                                        \
        __half* _Vd = Vs + (S) * KVSTG;                                        \
        _Pragma("unroll")                                                      \
        for (int _i = 0; _i < 2; _i++) {                                       \
            int _idx = tid + _i * 256;     /* 0..511 */                        \
            int _r = _idx >> 3;                                                \
            int _c8 = (_idx & 7) * 8;                                          \
            cp16(_Kd + _r * KST2 + _c8,                                        \
                 Kg + (size_t)(_k0 + _r) * HDIM + _c8, (_k0 + _r) < SEQ);      \
            cp16(_Vd + _r * VST2 + _c8,                                        \
                 VgT + (size_t)_r * SEQP + _k0 + _c8, (_k0 + _c8) < SEQ);      \
        }                                                                      \
        CP_COMMIT();                                                           \
    } while (0)

    float o[8][4];
#pragma unroll
    for (int od = 0; od < 8; od++)
#pragma unroll
        for (int i = 0; i < 4; i++) o[od][i] = 0.f;
    float m0v = -INFINITY, m1v = -INFINITY, l0 = 0.f, l1 = 0.f;

    int qr = w * 16 + lr;

    A_ISSUE(0, 0);   // includes Q copies
    A_ISSUE(1, 1);

    int st = 0;
    for (int t = 0; t < NT; t++) {
        if (t + 1 < NT) CP_WAIT1(); else CP_WAIT0();
        __syncthreads();
        if (t + 2 < NT) {
            int s2 = st + 2; if (s2 >= 3) s2 -= 3;
            A_ISSUE(t + 2, s2);
        }

        const __half* Ksb = Ks + st * KVSTG;
        const __half* Vsb = Vs + st * KVSTG;

        // S(16x64) = Q @ K^T
        float s[8][4];
#pragma unroll
        for (int nt = 0; nt < 8; nt++)
#pragma unroll
            for (int i = 0; i < 4; i++) s[nt][i] = 0.f;

#pragma unroll
        for (int kb = 0; kb < 4; kb++) {
            int kk = kb * 16;
            unsigned qf[4];
            ldsm4(qf, Qs + (w * 16 + lane15) * QST2 + kk + ak8);
            unsigned kf[4][4];
#pragma unroll
            for (int g = 0; g < 4; g++)
                ldsm4(kf[g], Ksb + (g * 16 + browl) * KST2 + kk + bk8);
#pragma unroll
            for (int nt = 0; nt < 8; nt++)
                mma_f16(s[nt], qf[0], qf[1], qf[2], qf[3],
                        kf[nt >> 1][(nt & 1) * 2], kf[nt >> 1][(nt & 1) * 2 + 1]);
        }

        // Mask only on the final partial tile
        if (t == NT - 1) {
#pragma unroll
            for (int nt = 0; nt < 8; nt++)
#pragma unroll
                for (int e = 0; e < 2; e++) {
                    int col = t * 64 + nt * 8 + 2 * lc + e;
                    if (col >= SEQ) { s[nt][e] = -INFINITY; s[nt][2 + e] = -INFINITY; }
                }
        }

        // In-warp row max
        float rmax0 = -INFINITY, rmax1 = -INFINITY;
#pragma unroll
        for (int nt = 0; nt < 8; nt++) {
            rmax0 = fmaxf(rmax0, fmaxf(s[nt][0], s[nt][1]));
            rmax1 = fmaxf(rmax1, fmaxf(s[nt][2], s[nt][3]));
        }
        rmax0 = fmaxf(rmax0, __shfl_xor_sync(0xffffffffu, rmax0, 1));
        rmax0 = fmaxf(rmax0, __shfl_xor_sync(0xffffffffu, rmax0, 2));
        rmax1 = fmaxf(rmax1, __shfl_xor_sync(0xffffffffu, rmax1, 1));
        rmax1 = fmaxf(rmax1, __shfl_xor_sync(0xffffffffu, rmax1, 2));

        float mn0 = fmaxf(m0v, rmax0);
        float mn1 = fmaxf(m1v, rmax1);
        float alpha0 = ex2(m0v - mn0);
        float alpha1 = ex2(m1v - mn1);
        m0v = mn0; m1v = mn1;

        float sum0 = 0.f, sum1 = 0.f;
#pragma unroll
        for (int nt = 0; nt < 8; nt++) {
#pragma unroll
            for (int e = 0; e < 2; e++) {
                float p0 = ex2(s[nt][e] - mn0);
                float p1 = ex2(s[nt][2 + e] - mn1);
                sum0 += p0; sum1 += p1;
                s[nt][e] = p0;
                s[nt][2 + e] = p1;
            }
        }
        sum0 += __shfl_xor_sync(0xffffffffu, sum0, 1);
        sum0 += __shfl_xor_sync(0xffffffffu, sum0, 2);
        sum1 += __shfl_xor_sync(0xffffffffu, sum1, 1);
        sum1 += __shfl_xor_sync(0xffffffffu, sum1, 2);
        l0 = l0 * alpha0 + sum0;
        l1 = l1 * alpha1 + sum1;

#pragma unroll
        for (int od = 0; od < 8; od++) {
            o[od][0] *= alpha0; o[od][1] *= alpha0;
            o[od][2] *= alpha1; o[od][3] *= alpha1;
        }

        // PV: A-frags = direct half2 packs of S C-frags (natural k16 layout);
        // V fragments via ldmatrix (4 x4 per k16 step for 8 d-octets).
#pragma unroll
        for (int kb = 0; kb < 4; kb++) {
            unsigned a0 = pack_h2(s[2 * kb][0],     s[2 * kb][1]);
            unsigned a1 = pack_h2(s[2 * kb][2],     s[2 * kb][3]);
            unsigned a2 = pack_h2(s[2 * kb + 1][0], s[2 * kb + 1][1]);
            unsigned a3 = pack_h2(s[2 * kb + 1][2], s[2 * kb + 1][3]);
            int kk = kb * 16;
            unsigned vf[4][4];
#pragma unroll
            for (int g = 0; g < 4; g++)
                ldsm4(vf[g], Vsb + (g * 16 + browl) * VST2 + kk + bk8);
#pragma unroll
            for (int od = 0; od < 8; od++)
                mma_f16(o[od], a0, a1, a2, a3,
                        vf[od >> 1][(od & 1) * 2], vf[od >> 1][(od & 1) * 2 + 1]);
        }
        if (++st == 3) st = 0;
    }

    // Epilogue: normalize, write fp16 ctx [B,S,D]
    float inv0 = 1.f / l0;
    float inv1 = 1.f / l1;
    int r0 = q0 + qr, r1 = r0 + 8;
#pragma unroll
    for (int od = 0; od < 8; od++) {
        int col = h * HDIM + od * 8 + lc * 2;
        if (r0 < SEQ)
            *(__half2*)&g_ch[((size_t)(b * SEQ + r0)) * DIM + col] =
                __floats2half2_rn(o[od][0] * inv0, o[od][1] * inv0);
        if (r1 < SEQ)
            *(__half2*)&g_ch[((size_t)(b * SEQ + r1)) * DIM + col] =
                __floats2half2_rn(o[od][2] * inv1, o[od][3] * inv1);
    }
}

// ---------------------------------------------------------------------------
extern "C" void kernel_launch(void* const* d_in, const int* in_sizes, int n_in,
                              void* d_out, int out_size)
{
    const float* x  = (const float*)d_in[0];
    const float* Wq = (const float*)d_in[1];
    const float* bq = (const float*)d_in[2];
    const float* Wk = (const float*)d_in[3];
    const float* bk = (const float*)d_in[4];
    const float* Wv = (const float*)d_in[5];
    const float* bv = (const float*)d_in[6];
    const float* Wo = (const float*)d_in[7];
    const float* bo = (const float*)d_in[8];
    float* out = (float*)d_out;

    round_x<<<(MROWS * DIM / 4 + 255) / 256, 256>>>(x);
    dim3 wtGrid(DIM / 32, DIM / 32, 4);
    round_wT<<<wtGrid, 256>>>(Wq, Wk, Wv, Wo);
    zero_vpad<<<(BATCH * HEADS * HDIM * (SEQP - SEQ) + 255) / 256, 256>>>();

    int gsm = 6 * HASTG * sizeof(__half);   // 110592
    cudaFuncSetAttribute(gemm_f16, cudaFuncAttributeMaxDynamicSharedMemorySize, gsm);

    dim3 qkvGrid((MROWS + 127) / 128, DIM / 128, 3);  // 86 x 8 x 3
    gemm_f16<<<qkvGrid, 256, gsm>>>(bq, bk, bv, nullptr, 0);

    int asm_ = (128 * QST2 + 6 * KVSTG) * sizeof(__half);  // 73728
    cudaFuncSetAttribute(attn_f16, cudaFuncAttributeMaxDynamicSharedMemorySize, asm_);
    dim3 attnGrid((SEQ + 127) / 128, BATCH * HEADS);  // 11 x 128
    attn_f16<<<attnGrid, 256, asm_>>>();

    dim3 oGrid((MROWS + 127) / 128, DIM / 128, 1);
    gemm_f16<<<oGrid, 256, gsm>>>(bo, nullptr, nullptr, out, 1);
}